// round 11
// baseline (speedup 1.0000x reference)
#include <cuda_runtime.h>
#include <cuda_fp16.h>
#include <math.h>
#include <stdint.h>

#define BB 2
#define HH 16
#define NSEQ 2048
#define DD 64
#define CC 1024
#define MM (BB*NSEQ)      /* 4096 */
#define K3 (3*CC)         /* 3072 */

// ---------------------------------------------------------------------------
// Scratch (__device__ globals; allocation-free rule)
// ---------------------------------------------------------------------------
__device__ __align__(256) __half g_qh[(size_t)BB*HH*NSEQ*DD];   // Q fp16, pre-scaled 0.125*log2e
__device__ __align__(256) __half g_kh[(size_t)BB*HH*NSEQ*DD];
__device__ __align__(256) __half g_vh[(size_t)BB*HH*NSEQ*DD];
__device__ __align__(256) __half g_xh[(size_t)MM*CC];           // x cast to fp16
__device__ __align__(256) __half g_Oh[(size_t)MM*CC];           // attention out, fp16
__device__ __align__(256) __half g_Bq[(size_t)K3*CC];           // W_qkv fp16 K-major
__device__ __align__(256) __half g_Bo[(size_t)CC*CC];           // W_out fp16 K-major

// ---------------------------------------------------------------------------
// PTX helpers (baseline sm_80 ISA — safe on plain sm_103 target)
// ---------------------------------------------------------------------------
__device__ __forceinline__ uint32_t smem_u32(const void* p) {
    uint32_t a;
    asm("{ .reg .u64 t; cvta.to.shared.u64 t, %1; cvt.u32.u64 %0, t; }"
        : "=r"(a) : "l"(p));
    return a;
}

#define SW128(off) ((off) ^ (((off) >> 3) & 0x70))

#define CP16(dst, src) \
    asm volatile("cp.async.cg.shared.global [%0], [%1], 16;" :: "r"(dst), "l"(src))
#define CP_COMMIT() asm volatile("cp.async.commit_group;" ::: "memory")
#define CP_WAIT1()  asm volatile("cp.async.wait_group 1;" ::: "memory")

__device__ __forceinline__ void ldsm4(uint32_t& r0, uint32_t& r1,
                                      uint32_t& r2, uint32_t& r3, uint32_t a) {
    asm volatile("ldmatrix.sync.aligned.m8n8.x4.shared.b16 {%0,%1,%2,%3}, [%4];"
        : "=r"(r0), "=r"(r1), "=r"(r2), "=r"(r3) : "r"(a));
}
__device__ __forceinline__ void ldsm4t(uint32_t& r0, uint32_t& r1,
                                       uint32_t& r2, uint32_t& r3, uint32_t a) {
    asm volatile("ldmatrix.sync.aligned.m8n8.x4.trans.shared.b16 {%0,%1,%2,%3}, [%4];"
        : "=r"(r0), "=r"(r1), "=r"(r2), "=r"(r3) : "r"(a));
}
__device__ __forceinline__ void mma_f16(float* c, const uint32_t* a, uint32_t b0, uint32_t b1) {
    asm volatile("mma.sync.aligned.m16n8k16.row.col.f32.f16.f16.f32 "
        "{%0,%1,%2,%3}, {%4,%5,%6,%7}, {%8,%9}, {%0,%1,%2,%3};"
        : "+f"(c[0]), "+f"(c[1]), "+f"(c[2]), "+f"(c[3])
        : "r"(a[0]), "r"(a[1]), "r"(a[2]), "r"(a[3]), "r"(b0), "r"(b1));
}

__device__ __forceinline__ uint32_t pack_h2(float lo, float hi) {
    __half2 h = __float22half2_rn(make_float2(lo, hi));
    return *(uint32_t*)&h;
}
__device__ __forceinline__ uint32_t ex2_h2(uint32_t x) {
    uint32_t r;
    asm("ex2.approx.f16x2 %0, %1;" : "=r"(r) : "r"(x));
    return r;
}
__device__ __forceinline__ float ex2_f32(float x) {
    float r;
    asm("ex2.approx.f32 %0, %1;" : "=f"(r) : "f"(x));
    return r;
}
__device__ __forceinline__ float h2sum(uint32_t p) {
    __half2 h; *(uint32_t*)&h = p;
    float2 f = __half22float2(h);
    return f.x + f.y;
}

// ---------------------------------------------------------------------------
// Fused prep: cast x->fp16, transpose+cast both weight matrices.
// ---------------------------------------------------------------------------
#define NB_CAST (MM * CC / 1024)          /* 4096 */
#define NB_TQ   ((CC / 32) * (K3 / 32))   /* 3072 */
#define NB_TO   ((CC / 32) * (CC / 32))   /* 1024 */

__global__ __launch_bounds__(256) void prep_kernel(
    const float* __restrict__ x,  const float* __restrict__ Wq,
    const float* __restrict__ Wo, __half* __restrict__ xh,
    __half* __restrict__ Bq, __half* __restrict__ Bo)
{
    const int bid = blockIdx.x, tid = threadIdx.x;
    if (bid < NB_CAST) {
        size_t idx4 = ((size_t)bid * 256 + tid) * 4;
        float4 v = *(const float4*)&x[idx4];
        __half2 a = __float22half2_rn(make_float2(v.x, v.y));
        __half2 b = __float22half2_rn(make_float2(v.z, v.w));
        *(uint2*)&xh[idx4] = make_uint2(*(uint32_t*)&a, *(uint32_t*)&b);
        return;
    }
    const float* W; __half* Bd; int N, b;
    if (bid < NB_CAST + NB_TQ) { b = bid - NB_CAST; W = Wq; Bd = Bq; N = K3; }
    else                       { b = bid - NB_CAST - NB_TQ; W = Wo; Bd = Bo; N = CC; }
    const int k0 = (b % 32) * 32;
    const int n0 = (b / 32) * 32;
    const int tx = tid & 31, ty = tid >> 5;

    __shared__ float t[32][33];
    #pragma unroll
    for (int i = 0; i < 4; i++)
        t[ty + i * 8][tx] = W[(size_t)(k0 + ty + i * 8) * N + n0 + tx];
    __syncthreads();
    #pragma unroll
    for (int i = 0; i < 4; i++) {
        int n = n0 + ty + i * 8, k = k0 + tx;
        Bd[(size_t)n * CC + k] = __float2half_rn(t[tx][ty + i * 8]);
    }
}

// ---------------------------------------------------------------------------
// HMMA GEMM: D[M][N] = A[M][1024] @ B[N][1024]^T (+bias)
// BM=128, BN=128, BK=64, 3-stage cp.async, 1 sync/iter, 2 CTAs/SM.
// MODE 0: qkv — fp16 to Qh/Kh/Vh in [b,h,n,d], Q pre-scaled 0.125*log2e.
// MODE 1: out proj — fp32 + bias to Cout.
// ---------------------------------------------------------------------------
#define STAGE_BYTES 32768
#define GEMM_SMEM (3 * STAGE_BYTES + 128)
#define KEXT 1024
#define KITERS (KEXT / 64)
#define QSCALE 0.18033688f   /* 0.125 * log2(e) */

template<int MODE>
__global__ __launch_bounds__(256, 2) void mma_gemm_kernel(
    const __half* __restrict__ A,
    const __half* __restrict__ Bm,
    const float* __restrict__ bias,
    float* __restrict__ Cout,
    __half* __restrict__ Qh, __half* __restrict__ Kh, __half* __restrict__ Vh)
{
    extern __shared__ char smraw[];
    char* smp = (char*)(((uintptr_t)smraw + 127) & ~(uintptr_t)127);
    const uint32_t sb = smem_u32(smp);

    const int tid = threadIdx.x;
    const int lane = tid & 31, wid = tid >> 5;
    const int wm = wid & 3, wn = wid >> 2;
    const int m0 = blockIdx.y * 128;
    const int n0 = blockIdx.x * 128;

    const char* gA = (const char*)A + (size_t)m0 * (KEXT * 2);
    const char* gB = (const char*)Bm + (size_t)n0 * (KEXT * 2);

    const int crow = tid >> 3;
    const int ccol = (tid & 7) * 16;

    auto load_tile = [&](int it, int buf) {
        const uint32_t ao = (uint32_t)buf * STAGE_BYTES;
        const uint32_t bo = ao + 16384u;
        const size_t kbyte = (size_t)it * 128;
        #pragma unroll
        for (int i = 0; i < 4; i++) {
            int r = crow + i * 32;
            CP16(sb + ao + SW128(r * 128 + ccol),
                 gA + (size_t)r * (KEXT * 2) + kbyte + ccol);
        }
        #pragma unroll
        for (int i = 0; i < 4; i++) {
            int r = crow + i * 32;
            CP16(sb + bo + SW128(r * 128 + ccol),
                 gB + (size_t)r * (KEXT * 2) + kbyte + ccol);
        }
    };

    float acc[2][8][4];
    #pragma unroll
    for (int mt = 0; mt < 2; mt++)
        #pragma unroll
        for (int nt = 0; nt < 8; nt++)
            #pragma unroll
            for (int j = 0; j < 4; j++) acc[mt][nt][j] = 0.f;

    load_tile(0, 0); CP_COMMIT();
    load_tile(1, 1); CP_COMMIT();

    int buf = 0;
    for (int it = 0; it < KITERS; it++) {
        CP_WAIT1();
        __syncthreads();
        if (it + 2 < KITERS) load_tile(it + 2, (buf + 2) % 3);
        CP_COMMIT();

        const uint32_t ao = (uint32_t)buf * STAGE_BYTES;
        const uint32_t bo = ao + 16384u;

        #pragma unroll
        for (int ks = 0; ks < 4; ks++) {
            uint32_t a[2][4];
            #pragma unroll
            for (int mt = 0; mt < 2; mt++) {
                uint32_t addr = sb + ao +
                    SW128((wm * 32 + mt * 16 + (lane & 15)) * 128 +
                          ks * 32 + ((lane >> 4) << 4));
                ldsm4(a[mt][0], a[mt][1], a[mt][2], a[mt][3], addr);
            }
            uint32_t b[8][2];
            #pragma unroll
            for (int p = 0; p < 4; p++) {
                uint32_t addr = sb + bo +
                    SW128((wn * 64 + p * 16 + (lane & 7) + ((lane >> 4) & 1) * 8) * 128 +
                          ks * 32 + ((lane >> 3) & 1) * 16);
                ldsm4(b[2 * p][0], b[2 * p][1], b[2 * p + 1][0], b[2 * p + 1][1], addr);
            }
            #pragma unroll
            for (int mt = 0; mt < 2; mt++)
                #pragma unroll
                for (int nt = 0; nt < 8; nt++)
                    mma_f16(acc[mt][nt], a[mt], b[nt][0], b[nt][1]);
        }
        buf = (buf + 1) % 3;
    }

    const int colbase = n0 + wn * 64;
    if (MODE == 0) {
        const int s = colbase >> 10;
        const int h = (colbase >> 6) & 15;
        __half* dst = (s == 0) ? Qh : ((s == 1) ? Kh : Vh);
        const float scl = (s == 0) ? QSCALE : 1.0f;
        #pragma unroll
        for (int mt = 0; mt < 2; mt++) {
            #pragma unroll
            for (int hf = 0; hf < 2; hf++) {
                int r = m0 + wm * 32 + mt * 16 + (lane >> 2) + hf * 8;
                int bidx = r >> 11, n = r & (NSEQ - 1);
                size_t rowoff = (((size_t)bidx * HH + h) * NSEQ + n) * DD;
                #pragma unroll
                for (int nt = 0; nt < 8; nt++) {
                    int dd = nt * 8 + (lane & 3) * 2;
                    float v0 = (acc[mt][nt][hf * 2 + 0] + bias[colbase + dd]) * scl;
                    float v1 = (acc[mt][nt][hf * 2 + 1] + bias[colbase + dd + 1]) * scl;
                    *(__half2*)&dst[rowoff + dd] =
                        __float22half2_rn(make_float2(v0, v1));
                }
            }
        }
    } else {
        #pragma unroll
        for (int mt = 0; mt < 2; mt++) {
            #pragma unroll
            for (int hf = 0; hf < 2; hf++) {
                int r = m0 + wm * 32 + mt * 16 + (lane >> 2) + hf * 8;
                float* crow2 = &Cout[(size_t)r * CC];
                #pragma unroll
                for (int nt = 0; nt < 8; nt++) {
                    int cc = colbase + nt * 8 + (lane & 3) * 2;
                    float2 o;
                    o.x = acc[mt][nt][hf * 2 + 0] + bias[cc];
                    o.y = acc[mt][nt][hf * 2 + 1] + bias[cc + 1];
                    *(float2*)&crow2[cc] = o;
                }
            }
        }
    }
}

// ---------------------------------------------------------------------------
// Flash attention, fp16 HMMA, log2 softmax, 3-stage KV pipeline, Q hoisted,
// rowsum in fp32 off the tensor pipe, V via ldmatrix.x4.trans. 2 CTAs/SM.
// ---------------------------------------------------------------------------
#define FL_SQ 0u
#define FL_KV(buf) (16384u + (uint32_t)(buf) * 16384u)   /* K 8KB then V 8KB */
#define FL_SMEM (65536 + 128)
#define NKB (NSEQ / 64)

__global__ __launch_bounds__(256, 2) void flash_mma_kernel(
    const __half* __restrict__ Qh, const __half* __restrict__ Kh,
    const __half* __restrict__ Vh, __half* __restrict__ Oh)
{
    extern __shared__ char smraw[];
    char* smp = (char*)(((uintptr_t)smraw + 127) & ~(uintptr_t)127);
    const uint32_t sb = smem_u32(smp);

    const int tid = threadIdx.x;
    const int lane = tid & 31, w = tid >> 5;
    const int bh = blockIdx.y;
    const int q0 = blockIdx.x * 128;
    const size_t base = (size_t)bh * NSEQ * DD;

    const char* gK = (const char*)(Kh + base);
    const char* gV = (const char*)(Vh + base);
    const int crow = tid >> 3;
    const int ccol = (tid & 7) * 16;

    auto load_kv = [&](int kc, int buf) {
        const size_t rb = (size_t)kc * 64 * 128;
        const uint32_t ko = FL_KV(buf), vo = ko + 8192u;
        #pragma unroll
        for (int i = 0; i < 2; i++) {
            int r = crow + i * 32;
            CP16(sb + ko + SW128(r * 128 + ccol), gK + rb + (size_t)r * 128 + ccol);
        }
        #pragma unroll
        for (int i = 0; i < 2; i++) {
            int r = crow + i * 32;
            CP16(sb + vo + SW128(r * 128 + ccol), gV + rb + (size_t)r * 128 + ccol);
        }
    };

    {
        const char* gQ = (const char*)(Qh + base + (size_t)q0 * DD);
        #pragma unroll
        for (int i = 0; i < 4; i++) {
            int r = crow + i * 32;
            CP16(sb + FL_SQ + SW128(r * 128 + ccol), gQ + (size_t)r * 128 + ccol);
        }
    }
    load_kv(0, 0); CP_COMMIT();
    load_kv(1, 1); CP_COMMIT();

    uint32_t qf[4][4];
    float oacc[8][4];
    #pragma unroll
    for (int nt = 0; nt < 8; nt++)
        #pragma unroll
        for (int j = 0; j < 4; j++) oacc[nt][j] = 0.f;
    float m0r = -1e30f, m1r = -1e30f, l0r = 0.f, l1r = 0.f;

    int buf = 0;
    for (int kc = 0; kc < NKB; kc++) {
        CP_WAIT1();
        __syncthreads();
        if (kc + 2 < NKB) load_kv(kc + 2, (buf + 2) % 3);
        CP_COMMIT();

        if (kc == 0) {
            #pragma unroll
            for (int ks = 0; ks < 4; ks++)
                ldsm4(qf[ks][0], qf[ks][1], qf[ks][2], qf[ks][3],
                      sb + FL_SQ + SW128((w * 16 + (lane & 15)) * 128 +
                                         ks * 32 + ((lane >> 4) << 4)));
        }
        const uint32_t ko = FL_KV(buf), vo = ko + 8192u;

        // ---- S = Q @ K^T (log2-domain logits) ----
        float sacc[8][4];
        #pragma unroll
        for (int nt = 0; nt < 8; nt++)
            #pragma unroll
            for (int j = 0; j < 4; j++) sacc[nt][j] = 0.f;

        #pragma unroll
        for (int ks = 0; ks < 4; ks++) {
            #pragma unroll
            for (int p = 0; p < 4; p++) {
                uint32_t b0, b1, b2, b3;
                ldsm4(b0, b1, b2, b3,
                      sb + ko + SW128((p * 16 + (lane & 7) + ((lane >> 4) & 1) * 8) * 128 +
                                      ks * 32 + ((lane >> 3) & 1) * 16));
                mma_f16(sacc[2 * p], qf[ks], b0, b1);
                mma_f16(sacc[2 * p + 1], qf[ks], b2, b3);
            }
        }

        // ---- online softmax (log2 domain) ----
        float mx0 = m0r, mx1 = m1r;
        #pragma unroll
        for (int nt = 0; nt < 8; nt++) {
            mx0 = fmaxf(mx0, fmaxf(sacc[nt][0], sacc[nt][1]));
            mx1 = fmaxf(mx1, fmaxf(sacc[nt][2], sacc[nt][3]));
        }
        mx0 = fmaxf(mx0, __shfl_xor_sync(0xffffffffu, mx0, 1));
        mx0 = fmaxf(mx0, __shfl_xor_sync(0xffffffffu, mx0, 2));
        mx1 = fmaxf(mx1, __shfl_xor_sync(0xffffffffu, mx1, 1));
        mx1 = fmaxf(mx1, __shfl_xor_sync(0xffffffffu, mx1, 2));

        float alpha0 = ex2_f32(m0r - mx0);
        float alpha1 = ex2_f32(m1r - mx1);
        m0r = mx0; m1r = mx1;

        // Skip O rescale when no row's max moved (alpha == 1.0 exactly).
        if (__any_sync(0xffffffffu, (alpha0 != 1.f) || (alpha1 != 1.f))) {
            #pragma unroll
            for (int nt = 0; nt < 8; nt++) {
                oacc[nt][0] *= alpha0; oacc[nt][1] *= alpha0;
                oacc[nt][2] *= alpha1; oacc[nt][3] *= alpha1;
            }
        }

        // ---- P = exp2(S - mx) fp16; rowsum in fp32 (off tensor); O += P@V ----
        float rs0 = 0.f, rs1 = 0.f;
        #pragma unroll
        for (int kt = 0; kt < 4; kt++) {
            uint32_t pa[4];
            pa[0] = ex2_h2(pack_h2(sacc[2 * kt][0] - mx0,     sacc[2 * kt][1] - mx0));
            pa[1] = ex2_h2(pack_h2(sacc[2 * kt][2] - mx1,     sacc[2 * kt][3] - mx1));
            pa[2] = ex2_h2(pack_h2(sacc[2 * kt + 1][0] - mx0, sacc[2 * kt + 1][1] - mx0));
            pa[3] = ex2_h2(pack_h2(sacc[2 * kt + 1][2] - mx1, sacc[2 * kt + 1][3] - mx1));
            rs0 += h2sum(pa[0]) + h2sum(pa[2]);
            rs1 += h2sum(pa[1]) + h2sum(pa[3]);
            #pragma unroll
            for (int ntp = 0; ntp < 4; ntp++) {
                uint32_t v0, v1, v2, v3;
                ldsm4t(v0, v1, v2, v3,
                       sb + vo + SW128((kt * 16 + (lane & 15)) * 128 +
                                       ntp * 32 + ((lane >> 4) << 4)));
                mma_f16(oacc[2 * ntp],     pa, v0, v1);
                mma_f16(oacc[2 * ntp + 1], pa, v2, v3);
            }
        }
        rs0 += __shfl_xor_sync(0xffffffffu, rs0, 1);
        rs0 += __shfl_xor_sync(0xffffffffu, rs0, 2);
        rs1 += __shfl_xor_sync(0xffffffffu, rs1, 1);
        rs1 += __shfl_xor_sync(0xffffffffu, rs1, 2);
        l0r = l0r * alpha0 + rs0;
        l1r = l1r * alpha1 + rs1;

        buf = (buf + 1) % 3;
    }

    // ---- epilogue: fp16 O into [B, N, C] ----
    const float inv0 = 1.f / l0r, inv1 = 1.f / l1r;
    const int b = bh >> 4, h = bh & 15;
    #pragma unroll
    for (int hf = 0; hf < 2; hf++) {
        int n = q0 + w * 16 + (lane >> 2) + hf * 8;
        float inv = hf ? inv1 : inv0;
        __half* orow = Oh + ((size_t)b * NSEQ + n) * CC;
        #pragma unroll
        for (int nt = 0; nt < 8; nt++) {
            int col = h * 64 + nt * 8 + (lane & 3) * 2;
            float o0 = oacc[nt][hf * 2 + 0] * inv;
            float o1 = oacc[nt][hf * 2 + 1] * inv;
            *(__half2*)&orow[col] = __float22half2_rn(make_float2(o0, o1));
        }
    }
}

// ---------------------------------------------------------------------------
// Launcher
// ---------------------------------------------------------------------------
extern "C" void kernel_launch(void* const* d_in, const int* in_sizes, int n_in,
                              void* d_out, int out_size)
{
    const float* x     = (const float*)d_in[0];
    const float* W_qkv = (const float*)d_in[1];
    const float* b_qkv = (const float*)d_in[2];
    const float* W_out = (const float*)d_in[3];
    const float* b_out = (const float*)d_in[4];
    float* out = (float*)d_out;

    __half *qh, *kh, *vh, *xh, *Oh, *Bq, *Bo;
    cudaGetSymbolAddress((void**)&qh, g_qh);
    cudaGetSymbolAddress((void**)&kh, g_kh);
    cudaGetSymbolAddress((void**)&vh, g_vh);
    cudaGetSymbolAddress((void**)&xh, g_xh);
    cudaGetSymbolAddress((void**)&Oh, g_Oh);
    cudaGetSymbolAddress((void**)&Bq, g_Bq);
    cudaGetSymbolAddress((void**)&Bo, g_Bo);

    cudaFuncSetAttribute((const void*)mma_gemm_kernel<0>,
                         cudaFuncAttributeMaxDynamicSharedMemorySize, GEMM_SMEM);
    cudaFuncSetAttribute((const void*)mma_gemm_kernel<1>,
                         cudaFuncAttributeMaxDynamicSharedMemorySize, GEMM_SMEM);
    cudaFuncSetAttribute(flash_mma_kernel,
                         cudaFuncAttributeMaxDynamicSharedMemorySize, FL_SMEM);

    // 1) fused prep: cast x; transpose+cast W_qkv, W_out
    prep_kernel<<<NB_CAST + NB_TQ + NB_TO, 256>>>(x, W_qkv, W_out, xh, Bq, Bo);
    // 2) QKV projection (HMMA fp16, K=1024) -> fp16 Q(log2-scaled)/K/V
    mma_gemm_kernel<0><<<dim3(K3 / 128, MM / 128), 256, GEMM_SMEM>>>(
        xh, Bq, b_qkv, nullptr, qh, kh, vh);
    // 3) Flash attention (fp16 HMMA, exp2 softmax) -> Oh [B,N,C] fp16
    flash_mma_kernel<<<dim3(NSEQ / 128, BB * HH), 256, FL_SMEM>>>(qh, kh, vh, Oh);
    // 4) Output projection (HMMA fp16, K=1024) -> out
    mma_gemm_kernel<1><<<dim3(CC / 128, MM / 128), 256, GEMM_SMEM>>>(
        Oh, Bo, b_out, out, nullptr, nullptr, nullptr);
}

// round 12
// speedup vs baseline: 1.5325x; 1.5325x over previous
#include <cuda_runtime.h>
#include <cuda_fp16.h>
#include <math.h>
#include <stdint.h>

#define BB 2
#define HH 16
#define NSEQ 2048
#define DD 64
#define CC 1024
#define MM (BB*NSEQ)      /* 4096 */
#define K3 (3*CC)         /* 3072 */

// ---------------------------------------------------------------------------
// Scratch (__device__ globals; allocation-free rule)
// ---------------------------------------------------------------------------
__device__ __align__(256) __half g_qh[(size_t)BB*HH*NSEQ*DD];   // Q fp16, pre-scaled 0.125*log2e
__device__ __align__(256) __half g_kh[(size_t)BB*HH*NSEQ*DD];
__device__ __align__(256) __half g_vh[(size_t)BB*HH*NSEQ*DD];
__device__ __align__(256) __half g_xh[(size_t)MM*CC];           // x cast to fp16
__device__ __align__(256) __half g_Oh[(size_t)MM*CC];           // attention out, fp16
__device__ __align__(256) __half g_Bq[(size_t)K3*CC];           // W_qkv fp16 K-major
__device__ __align__(256) __half g_Bo[(size_t)CC*CC];           // W_out fp16 K-major

// ---------------------------------------------------------------------------
// PTX helpers (baseline sm_80 ISA — safe on plain sm_103 target)
// ---------------------------------------------------------------------------
__device__ __forceinline__ uint32_t smem_u32(const void* p) {
    uint32_t a;
    asm("{ .reg .u64 t; cvta.to.shared.u64 t, %1; cvt.u32.u64 %0, t; }"
        : "=r"(a) : "l"(p));
    return a;
}

#define SW128(off) ((off) ^ (((off) >> 3) & 0x70))

#define CP16(dst, src) \
    asm volatile("cp.async.cg.shared.global [%0], [%1], 16;" :: "r"(dst), "l"(src))
#define CP_COMMIT() asm volatile("cp.async.commit_group;" ::: "memory")
#define CP_WAIT1()  asm volatile("cp.async.wait_group 1;" ::: "memory")

__device__ __forceinline__ void ldsm4(uint32_t& r0, uint32_t& r1,
                                      uint32_t& r2, uint32_t& r3, uint32_t a) {
    asm volatile("ldmatrix.sync.aligned.m8n8.x4.shared.b16 {%0,%1,%2,%3}, [%4];"
        : "=r"(r0), "=r"(r1), "=r"(r2), "=r"(r3) : "r"(a));
}
__device__ __forceinline__ void ldsm4t(uint32_t& r0, uint32_t& r1,
                                       uint32_t& r2, uint32_t& r3, uint32_t a) {
    asm volatile("ldmatrix.sync.aligned.m8n8.x4.trans.shared.b16 {%0,%1,%2,%3}, [%4];"
        : "=r"(r0), "=r"(r1), "=r"(r2), "=r"(r3) : "r"(a));
}
__device__ __forceinline__ void mma_f16(float* c, const uint32_t* a, uint32_t b0, uint32_t b1) {
    asm volatile("mma.sync.aligned.m16n8k16.row.col.f32.f16.f16.f32 "
        "{%0,%1,%2,%3}, {%4,%5,%6,%7}, {%8,%9}, {%0,%1,%2,%3};"
        : "+f"(c[0]), "+f"(c[1]), "+f"(c[2]), "+f"(c[3])
        : "r"(a[0]), "r"(a[1]), "r"(a[2]), "r"(a[3]), "r"(b0), "r"(b1));
}

__device__ __forceinline__ uint32_t pack_h2(float lo, float hi) {
    __half2 h = __float22half2_rn(make_float2(lo, hi));
    return *(uint32_t*)&h;
}
__device__ __forceinline__ uint32_t ex2_h2(uint32_t x) {
    uint32_t r;
    asm("ex2.approx.f16x2 %0, %1;" : "=r"(r) : "r"(x));
    return r;
}
__device__ __forceinline__ float ex2_f32(float x) {
    float r;
    asm("ex2.approx.f32 %0, %1;" : "=f"(r) : "f"(x));
    return r;
}
__device__ __forceinline__ float h2sum(uint32_t p) {
    __half2 h; *(uint32_t*)&h = p;
    float2 f = __half22float2(h);
    return f.x + f.y;
}

// ---------------------------------------------------------------------------
// Fused prep: cast x->fp16, transpose+cast both weight matrices.
// ---------------------------------------------------------------------------
#define NB_CAST (MM * CC / 1024)          /* 4096 */
#define NB_TQ   ((CC / 32) * (K3 / 32))   /* 3072 */
#define NB_TO   ((CC / 32) * (CC / 32))   /* 1024 */

__global__ __launch_bounds__(256) void prep_kernel(
    const float* __restrict__ x,  const float* __restrict__ Wq,
    const float* __restrict__ Wo, __half* __restrict__ xh,
    __half* __restrict__ Bq, __half* __restrict__ Bo)
{
    const int bid = blockIdx.x, tid = threadIdx.x;
    if (bid < NB_CAST) {
        size_t idx4 = ((size_t)bid * 256 + tid) * 4;
        float4 v = *(const float4*)&x[idx4];
        __half2 a = __float22half2_rn(make_float2(v.x, v.y));
        __half2 b = __float22half2_rn(make_float2(v.z, v.w));
        *(uint2*)&xh[idx4] = make_uint2(*(uint32_t*)&a, *(uint32_t*)&b);
        return;
    }
    const float* W; __half* Bd; int N, b;
    if (bid < NB_CAST + NB_TQ) { b = bid - NB_CAST; W = Wq; Bd = Bq; N = K3; }
    else                       { b = bid - NB_CAST - NB_TQ; W = Wo; Bd = Bo; N = CC; }
    const int k0 = (b % 32) * 32;
    const int n0 = (b / 32) * 32;
    const int tx = tid & 31, ty = tid >> 5;

    __shared__ float t[32][33];
    #pragma unroll
    for (int i = 0; i < 4; i++)
        t[ty + i * 8][tx] = W[(size_t)(k0 + ty + i * 8) * N + n0 + tx];
    __syncthreads();
    #pragma unroll
    for (int i = 0; i < 4; i++) {
        int n = n0 + ty + i * 8, k = k0 + tx;
        Bd[(size_t)n * CC + k] = __float2half_rn(t[tx][ty + i * 8]);
    }
}

// ---------------------------------------------------------------------------
// HMMA GEMM: D[M][N] = A[M][1024] @ B[N][1024]^T (+bias)
// BM=128, BN=128, BK=64, 3-stage cp.async, 1 sync/iter, 2 CTAs/SM.
// MODE 0: qkv — fp16 to Qh/Kh/Vh in [b,h,n,d], Q pre-scaled 0.125*log2e.
// MODE 1: out proj — fp32 + bias to Cout.
// ---------------------------------------------------------------------------
#define STAGE_BYTES 32768
#define GEMM_SMEM (3 * STAGE_BYTES + 128)
#define KEXT 1024
#define KITERS (KEXT / 64)
#define QSCALE 0.18033688f   /* 0.125 * log2(e) */

template<int MODE>
__global__ __launch_bounds__(256, 2) void mma_gemm_kernel(
    const __half* __restrict__ A,
    const __half* __restrict__ Bm,
    const float* __restrict__ bias,
    float* __restrict__ Cout,
    __half* __restrict__ Qh, __half* __restrict__ Kh, __half* __restrict__ Vh)
{
    extern __shared__ char smraw[];
    char* smp = (char*)(((uintptr_t)smraw + 127) & ~(uintptr_t)127);
    const uint32_t sb = smem_u32(smp);

    const int tid = threadIdx.x;
    const int lane = tid & 31, wid = tid >> 5;
    const int wm = wid & 3, wn = wid >> 2;
    const int m0 = blockIdx.y * 128;
    const int n0 = blockIdx.x * 128;

    const char* gA = (const char*)A + (size_t)m0 * (KEXT * 2);
    const char* gB = (const char*)Bm + (size_t)n0 * (KEXT * 2);

    const int crow = tid >> 3;
    const int ccol = (tid & 7) * 16;

    auto load_tile = [&](int it, int buf) {
        const uint32_t ao = (uint32_t)buf * STAGE_BYTES;
        const uint32_t bo = ao + 16384u;
        const size_t kbyte = (size_t)it * 128;
        #pragma unroll
        for (int i = 0; i < 4; i++) {
            int r = crow + i * 32;
            CP16(sb + ao + SW128(r * 128 + ccol),
                 gA + (size_t)r * (KEXT * 2) + kbyte + ccol);
        }
        #pragma unroll
        for (int i = 0; i < 4; i++) {
            int r = crow + i * 32;
            CP16(sb + bo + SW128(r * 128 + ccol),
                 gB + (size_t)r * (KEXT * 2) + kbyte + ccol);
        }
    };

    float acc[2][8][4];
    #pragma unroll
    for (int mt = 0; mt < 2; mt++)
        #pragma unroll
        for (int nt = 0; nt < 8; nt++)
            #pragma unroll
            for (int j = 0; j < 4; j++) acc[mt][nt][j] = 0.f;

    load_tile(0, 0); CP_COMMIT();
    load_tile(1, 1); CP_COMMIT();

    int buf = 0;
    for (int it = 0; it < KITERS; it++) {
        CP_WAIT1();
        __syncthreads();
        if (it + 2 < KITERS) load_tile(it + 2, (buf + 2) % 3);
        CP_COMMIT();

        const uint32_t ao = (uint32_t)buf * STAGE_BYTES;
        const uint32_t bo = ao + 16384u;

        #pragma unroll
        for (int ks = 0; ks < 4; ks++) {
            uint32_t a[2][4];
            #pragma unroll
            for (int mt = 0; mt < 2; mt++) {
                uint32_t addr = sb + ao +
                    SW128((wm * 32 + mt * 16 + (lane & 15)) * 128 +
                          ks * 32 + ((lane >> 4) << 4));
                ldsm4(a[mt][0], a[mt][1], a[mt][2], a[mt][3], addr);
            }
            uint32_t b[8][2];
            #pragma unroll
            for (int p = 0; p < 4; p++) {
                uint32_t addr = sb + bo +
                    SW128((wn * 64 + p * 16 + (lane & 7) + ((lane >> 4) & 1) * 8) * 128 +
                          ks * 32 + ((lane >> 3) & 1) * 16);
                ldsm4(b[2 * p][0], b[2 * p][1], b[2 * p + 1][0], b[2 * p + 1][1], addr);
            }
            #pragma unroll
            for (int mt = 0; mt < 2; mt++)
                #pragma unroll
                for (int nt = 0; nt < 8; nt++)
                    mma_f16(acc[mt][nt], a[mt], b[nt][0], b[nt][1]);
        }
        buf = (buf + 1) % 3;
    }

    const int colbase = n0 + wn * 64;
    if (MODE == 0) {
        const int s = colbase >> 10;
        const int h = (colbase >> 6) & 15;
        __half* dst = (s == 0) ? Qh : ((s == 1) ? Kh : Vh);
        const float scl = (s == 0) ? QSCALE : 1.0f;
        #pragma unroll
        for (int mt = 0; mt < 2; mt++) {
            #pragma unroll
            for (int hf = 0; hf < 2; hf++) {
                int r = m0 + wm * 32 + mt * 16 + (lane >> 2) + hf * 8;
                int bidx = r >> 11, n = r & (NSEQ - 1);
                size_t rowoff = (((size_t)bidx * HH + h) * NSEQ + n) * DD;
                #pragma unroll
                for (int nt = 0; nt < 8; nt++) {
                    int dd = nt * 8 + (lane & 3) * 2;
                    float v0 = (acc[mt][nt][hf * 2 + 0] + bias[colbase + dd]) * scl;
                    float v1 = (acc[mt][nt][hf * 2 + 1] + bias[colbase + dd + 1]) * scl;
                    *(__half2*)&dst[rowoff + dd] =
                        __float22half2_rn(make_float2(v0, v1));
                }
            }
        }
    } else {
        #pragma unroll
        for (int mt = 0; mt < 2; mt++) {
            #pragma unroll
            for (int hf = 0; hf < 2; hf++) {
                int r = m0 + wm * 32 + mt * 16 + (lane >> 2) + hf * 8;
                float* crow2 = &Cout[(size_t)r * CC];
                #pragma unroll
                for (int nt = 0; nt < 8; nt++) {
                    int cc = colbase + nt * 8 + (lane & 3) * 2;
                    float2 o;
                    o.x = acc[mt][nt][hf * 2 + 0] + bias[cc];
                    o.y = acc[mt][nt][hf * 2 + 1] + bias[cc + 1];
                    *(float2*)&crow2[cc] = o;
                }
            }
        }
    }
}

// ---------------------------------------------------------------------------
// Flash attention, fp16 HMMA, log2 softmax, 3-stage KV pipeline, Q hoisted,
// rowsum in fp32 off the tensor pipe, V via ldmatrix.x4.trans. 2 CTAs/SM.
// ---------------------------------------------------------------------------
#define FL_SQ 0u
#define FL_KV(buf) (16384u + (uint32_t)(buf) * 16384u)   /* K 8KB then V 8KB */
#define FL_SMEM (65536 + 128)
#define NKB (NSEQ / 64)

__global__ __launch_bounds__(256, 2) void flash_mma_kernel(
    const __half* __restrict__ Qh, const __half* __restrict__ Kh,
    const __half* __restrict__ Vh, __half* __restrict__ Oh)
{
    extern __shared__ char smraw[];
    char* smp = (char*)(((uintptr_t)smraw + 127) & ~(uintptr_t)127);
    const uint32_t sb = smem_u32(smp);

    const int tid = threadIdx.x;
    const int lane = tid & 31, w = tid >> 5;
    const int bh = blockIdx.y;
    const int q0 = blockIdx.x * 128;
    const size_t base = (size_t)bh * NSEQ * DD;

    const char* gK = (const char*)(Kh + base);
    const char* gV = (const char*)(Vh + base);
    const int crow = tid >> 3;
    const int ccol = (tid & 7) * 16;

    auto load_kv = [&](int kc, int buf) {
        const size_t rb = (size_t)kc * 64 * 128;
        const uint32_t ko = FL_KV(buf), vo = ko + 8192u;
        #pragma unroll
        for (int i = 0; i < 2; i++) {
            int r = crow + i * 32;
            CP16(sb + ko + SW128(r * 128 + ccol), gK + rb + (size_t)r * 128 + ccol);
        }
        #pragma unroll
        for (int i = 0; i < 2; i++) {
            int r = crow + i * 32;
            CP16(sb + vo + SW128(r * 128 + ccol), gV + rb + (size_t)r * 128 + ccol);
        }
    };

    {
        const char* gQ = (const char*)(Qh + base + (size_t)q0 * DD);
        #pragma unroll
        for (int i = 0; i < 4; i++) {
            int r = crow + i * 32;
            CP16(sb + FL_SQ + SW128(r * 128 + ccol), gQ + (size_t)r * 128 + ccol);
        }
    }
    load_kv(0, 0); CP_COMMIT();
    load_kv(1, 1); CP_COMMIT();

    uint32_t qf[4][4];
    float oacc[8][4];
    #pragma unroll
    for (int nt = 0; nt < 8; nt++)
        #pragma unroll
        for (int j = 0; j < 4; j++) oacc[nt][j] = 0.f;
    float m0r = -1e30f, m1r = -1e30f, l0r = 0.f, l1r = 0.f;

    int buf = 0;
    for (int kc = 0; kc < NKB; kc++) {
        CP_WAIT1();
        __syncthreads();
        if (kc + 2 < NKB) load_kv(kc + 2, (buf + 2) % 3);
        CP_COMMIT();

        if (kc == 0) {
            #pragma unroll
            for (int ks = 0; ks < 4; ks++)
                ldsm4(qf[ks][0], qf[ks][1], qf[ks][2], qf[ks][3],
                      sb + FL_SQ + SW128((w * 16 + (lane & 15)) * 128 +
                                         ks * 32 + ((lane >> 4) << 4)));
        }
        const uint32_t ko = FL_KV(buf), vo = ko + 8192u;

        // ---- S = Q @ K^T (log2-domain logits) ----
        float sacc[8][4];
        #pragma unroll
        for (int nt = 0; nt < 8; nt++)
            #pragma unroll
            for (int j = 0; j < 4; j++) sacc[nt][j] = 0.f;

        #pragma unroll
        for (int ks = 0; ks < 4; ks++) {
            #pragma unroll
            for (int p = 0; p < 4; p++) {
                uint32_t b0, b1, b2, b3;
                ldsm4(b0, b1, b2, b3,
                      sb + ko + SW128((p * 16 + (lane & 7) + ((lane >> 4) & 1) * 8) * 128 +
                                      ks * 32 + ((lane >> 3) & 1) * 16));
                mma_f16(sacc[2 * p], qf[ks], b0, b1);
                mma_f16(sacc[2 * p + 1], qf[ks], b2, b3);
            }
        }

        // ---- online softmax (log2 domain) ----
        float mx0 = m0r, mx1 = m1r;
        #pragma unroll
        for (int nt = 0; nt < 8; nt++) {
            mx0 = fmaxf(mx0, fmaxf(sacc[nt][0], sacc[nt][1]));
            mx1 = fmaxf(mx1, fmaxf(sacc[nt][2], sacc[nt][3]));
        }
        mx0 = fmaxf(mx0, __shfl_xor_sync(0xffffffffu, mx0, 1));
        mx0 = fmaxf(mx0, __shfl_xor_sync(0xffffffffu, mx0, 2));
        mx1 = fmaxf(mx1, __shfl_xor_sync(0xffffffffu, mx1, 1));
        mx1 = fmaxf(mx1, __shfl_xor_sync(0xffffffffu, mx1, 2));

        float alpha0 = ex2_f32(m0r - mx0);
        float alpha1 = ex2_f32(m1r - mx1);
        m0r = mx0; m1r = mx1;

        // Skip O rescale when no row's max moved (alpha == 1.0 exactly).
        if (__any_sync(0xffffffffu, (alpha0 != 1.f) || (alpha1 != 1.f))) {
            #pragma unroll
            for (int nt = 0; nt < 8; nt++) {
                oacc[nt][0] *= alpha0; oacc[nt][1] *= alpha0;
                oacc[nt][2] *= alpha1; oacc[nt][3] *= alpha1;
            }
        }

        // ---- P = exp2(S - mx) fp16; rowsum in fp32 (off tensor); O += P@V ----
        float rs0 = 0.f, rs1 = 0.f;
        #pragma unroll
        for (int kt = 0; kt < 4; kt++) {
            uint32_t pa[4];
            pa[0] = ex2_h2(pack_h2(sacc[2 * kt][0] - mx0,     sacc[2 * kt][1] - mx0));
            pa[1] = ex2_h2(pack_h2(sacc[2 * kt][2] - mx1,     sacc[2 * kt][3] - mx1));
            pa[2] = ex2_h2(pack_h2(sacc[2 * kt + 1][0] - mx0, sacc[2 * kt + 1][1] - mx0));
            pa[3] = ex2_h2(pack_h2(sacc[2 * kt + 1][2] - mx1, sacc[2 * kt + 1][3] - mx1));
            rs0 += h2sum(pa[0]) + h2sum(pa[2]);
            rs1 += h2sum(pa[1]) + h2sum(pa[3]);
            #pragma unroll
            for (int ntp = 0; ntp < 4; ntp++) {
                uint32_t v0, v1, v2, v3;
                ldsm4t(v0, v1, v2, v3,
                       sb + vo + SW128((kt * 16 + (lane & 15)) * 128 +
                                       ntp * 32 + ((lane >> 4) << 4)));
                mma_f16(oacc[2 * ntp],     pa, v0, v1);
                mma_f16(oacc[2 * ntp + 1], pa, v2, v3);
            }
        }
        rs0 += __shfl_xor_sync(0xffffffffu, rs0, 1);
        rs0 += __shfl_xor_sync(0xffffffffu, rs0, 2);
        rs1 += __shfl_xor_sync(0xffffffffu, rs1, 1);
        rs1 += __shfl_xor_sync(0xffffffffu, rs1, 2);
        l0r = l0r * alpha0 + rs0;
        l1r = l1r * alpha1 + rs1;

        buf = (buf + 1) % 3;
    }

    // ---- epilogue: fp16 O into [B, N, C] ----
    const float inv0 = 1.f / l0r, inv1 = 1.f / l1r;
    const int b = bh >> 4, h = bh & 15;
    #pragma unroll
    for (int hf = 0; hf < 2; hf++) {
        int n = q0 + w * 16 + (lane >> 2) + hf * 8;
        float inv = hf ? inv1 : inv0;
        __half* orow = Oh + ((size_t)b * NSEQ + n) * CC;
        #pragma unroll
        for (int nt = 0; nt < 8; nt++) {
            int col = h * 64 + nt * 8 + (lane & 3) * 2;
            float o0 = oacc[nt][hf * 2 + 0] * inv;
            float o1 = oacc[nt][hf * 2 + 1] * inv;
            *(__half2*)&orow[col] = __float22half2_rn(make_float2(o0, o1));
        }
    }
}

// ---------------------------------------------------------------------------
// Launcher
// ---------------------------------------------------------------------------
extern "C" void kernel_launch(void* const* d_in, const int* in_sizes, int n_in,
                              void* d_out, int out_size)
{
    const float* x     = (const float*)d_in[0];
    const float* W_qkv = (const float*)d_in[1];
    const float* b_qkv = (const float*)d_in[2];
    const float* W_out = (const float*)d_in[3];
    const float* b_out = (const float*)d_in[4];
    float* out = (float*)d_out;

    __half *qh, *kh, *vh, *xh, *Oh, *Bq, *Bo;
    cudaGetSymbolAddress((void**)&qh, g_qh);
    cudaGetSymbolAddress((void**)&kh, g_kh);
    cudaGetSymbolAddress((void**)&vh, g_vh);
    cudaGetSymbolAddress((void**)&xh, g_xh);
    cudaGetSymbolAddress((void**)&Oh, g_Oh);
    cudaGetSymbolAddress((void**)&Bq, g_Bq);
    cudaGetSymbolAddress((void**)&Bo, g_Bo);

    cudaFuncSetAttribute((const void*)mma_gemm_kernel<0>,
                         cudaFuncAttributeMaxDynamicSharedMemorySize, GEMM_SMEM);
    cudaFuncSetAttribute((const void*)mma_gemm_kernel<1>,
                         cudaFuncAttributeMaxDynamicSharedMemorySize, GEMM_SMEM);
    cudaFuncSetAttribute(flash_mma_kernel,
                         cudaFuncAttributeMaxDynamicSharedMemorySize, FL_SMEM);

    // 1) fused prep: cast x; transpose+cast W_qkv, W_out
    prep_kernel<<<NB_CAST + NB_TQ + NB_TO, 256>>>(x, W_qkv, W_out, xh, Bq, Bo);
    // 2) QKV projection (HMMA fp16, K=1024) -> fp16 Q(log2-scaled)/K/V
    mma_gemm_kernel<0><<<dim3(K3 / 128, MM / 128), 256, GEMM_SMEM>>>(
        xh, Bq, b_qkv, nullptr, qh, kh, vh);
    // 3) Flash attention (fp16 HMMA, exp2 softmax) -> Oh [B,N,C] fp16
    flash_mma_kernel<<<dim3(NSEQ / 128, BB * HH), 256, FL_SMEM>>>(qh, kh, vh, Oh);
    // 4) Output projection (HMMA fp16, K=1024) -> out
    mma_gemm_kernel<1><<<dim3(CC / 128, MM / 128), 256, GEMM_SMEM>>>(
        Oh, Bo, b_out, out, nullptr, nullptr, nullptr);
}

// round 13
// speedup vs baseline: 1.5630x; 1.0199x over previous
#include <cuda_runtime.h>
#include <cuda_fp16.h>
#include <math.h>
#include <stdint.h>

#define BB 2
#define HH 16
#define NSEQ 2048
#define DD 64
#define CC 1024
#define MM (BB*NSEQ)      /* 4096 */
#define K3 (3*CC)         /* 3072 */

// ---------------------------------------------------------------------------
// Scratch (__device__ globals; allocation-free rule)
// ---------------------------------------------------------------------------
__device__ __align__(256) __half g_qh[(size_t)BB*HH*NSEQ*DD];   // Q fp16, pre-scaled 0.125*log2e
__device__ __align__(256) __half g_kh[(size_t)BB*HH*NSEQ*DD];
__device__ __align__(256) __half g_vh[(size_t)BB*HH*NSEQ*DD];
__device__ __align__(256) __half g_xh[(size_t)MM*CC];           // x cast to fp16
__device__ __align__(256) __half g_Oh[(size_t)MM*CC];           // attention out, fp16
__device__ __align__(256) __half g_Bq[(size_t)CC*K3];           // W_qkv fp16, natural [k][n]
__device__ __align__(256) __half g_Bo[(size_t)CC*CC];           // W_out fp16, natural [k][n]

// ---------------------------------------------------------------------------
// PTX helpers (baseline sm_80 ISA — safe on plain sm_103 target)
// ---------------------------------------------------------------------------
__device__ __forceinline__ uint32_t smem_u32(const void* p) {
    uint32_t a;
    asm("{ .reg .u64 t; cvta.to.shared.u64 t, %1; cvt.u32.u64 %0, t; }"
        : "=r"(a) : "l"(p));
    return a;
}

#define SW128(off) ((off) ^ (((off) >> 3) & 0x70))

#define CP16(dst, src) \
    asm volatile("cp.async.cg.shared.global [%0], [%1], 16;" :: "r"(dst), "l"(src))
#define CP_COMMIT() asm volatile("cp.async.commit_group;" ::: "memory")
#define CP_WAIT1()  asm volatile("cp.async.wait_group 1;" ::: "memory")

__device__ __forceinline__ void ldsm4(uint32_t& r0, uint32_t& r1,
                                      uint32_t& r2, uint32_t& r3, uint32_t a) {
    asm volatile("ldmatrix.sync.aligned.m8n8.x4.shared.b16 {%0,%1,%2,%3}, [%4];"
        : "=r"(r0), "=r"(r1), "=r"(r2), "=r"(r3) : "r"(a));
}
__device__ __forceinline__ void ldsm4t(uint32_t& r0, uint32_t& r1,
                                       uint32_t& r2, uint32_t& r3, uint32_t a) {
    asm volatile("ldmatrix.sync.aligned.m8n8.x4.trans.shared.b16 {%0,%1,%2,%3}, [%4];"
        : "=r"(r0), "=r"(r1), "=r"(r2), "=r"(r3) : "r"(a));
}
__device__ __forceinline__ void mma_f16(float* c, const uint32_t* a, uint32_t b0, uint32_t b1) {
    asm volatile("mma.sync.aligned.m16n8k16.row.col.f32.f16.f16.f32 "
        "{%0,%1,%2,%3}, {%4,%5,%6,%7}, {%8,%9}, {%0,%1,%2,%3};"
        : "+f"(c[0]), "+f"(c[1]), "+f"(c[2]), "+f"(c[3])
        : "r"(a[0]), "r"(a[1]), "r"(a[2]), "r"(a[3]), "r"(b0), "r"(b1));
}

__device__ __forceinline__ uint32_t pack_h2(float lo, float hi) {
    __half2 h = __float22half2_rn(make_float2(lo, hi));
    return *(uint32_t*)&h;
}
__device__ __forceinline__ uint32_t ex2_h2(uint32_t x) {
    uint32_t r;
    asm("ex2.approx.f16x2 %0, %1;" : "=r"(r) : "r"(x));
    return r;
}
__device__ __forceinline__ float ex2_f32(float x) {
    float r;
    asm("ex2.approx.f32 %0, %1;" : "=f"(r) : "f"(x));
    return r;
}

// ---------------------------------------------------------------------------
// Fused prep: pure elementwise fp32->fp16 casts (x, W_qkv, W_out). No
// transposes — GEMMs read B from natural [k][n] layout via trans-ldmatrix.
// Each block casts 1024 elements (256 threads x 4).
// ---------------------------------------------------------------------------
#define NB_X  (MM * CC / 1024)    /* 4096 */
#define NB_WQ (CC * K3 / 1024)    /* 3072 */
#define NB_WO (CC * CC / 1024)    /* 1024 */

__global__ __launch_bounds__(256) void prep_kernel(
    const float* __restrict__ x,  const float* __restrict__ Wq,
    const float* __restrict__ Wo, __half* __restrict__ xh,
    __half* __restrict__ Bq, __half* __restrict__ Bo)
{
    const int bid = blockIdx.x, tid = threadIdx.x;
    const float* src;
    __half* dst;
    int b;
    if (bid < NB_X)            { b = bid;                 src = x;  dst = xh; }
    else if (bid < NB_X+NB_WQ) { b = bid - NB_X;          src = Wq; dst = Bq; }
    else                       { b = bid - NB_X - NB_WQ;  src = Wo; dst = Bo; }
    size_t idx4 = ((size_t)b * 256 + tid) * 4;
    float4 v = *(const float4*)&src[idx4];
    __half2 a = __float22half2_rn(make_float2(v.x, v.y));
    __half2 c = __float22half2_rn(make_float2(v.z, v.w));
    *(uint2*)&dst[idx4] = make_uint2(*(uint32_t*)&a, *(uint32_t*)&c);
}

// ---------------------------------------------------------------------------
// HMMA GEMM: D[M][N] = A[M][1024] @ B_kn[1024][N] (+bias), B natural [k][n].
// BM=128, BN=128, BK=64, 3-stage cp.async, 1 sync/iter, 2 CTAs/SM.
// B smem: two 64-n-col subtiles (128B rows, SW128), fragments via ldsm4t.
// MODE 0: qkv (NTOT=3072) — fp16 to Qh/Kh/Vh in [b,h,n,d], Q scaled QSCALE.
// MODE 1: out proj (NTOT=1024) — fp32 + bias to Cout.
// ---------------------------------------------------------------------------
#define STAGE_BYTES 32768
#define GEMM_SMEM (3 * STAGE_BYTES + 128)
#define KEXT 1024
#define KITERS (KEXT / 64)
#define QSCALE 0.18033688f   /* 0.125 * log2(e) */

template<int MODE>
__global__ __launch_bounds__(256, 2) void mma_gemm_kernel(
    const __half* __restrict__ A,
    const __half* __restrict__ Bm,
    const float* __restrict__ bias,
    float* __restrict__ Cout,
    __half* __restrict__ Qh, __half* __restrict__ Kh, __half* __restrict__ Vh)
{
    constexpr int NTOT = (MODE == 0) ? K3 : CC;
    extern __shared__ char smraw[];
    char* smp = (char*)(((uintptr_t)smraw + 127) & ~(uintptr_t)127);
    const uint32_t sb = smem_u32(smp);

    const int tid = threadIdx.x;
    const int lane = tid & 31, wid = tid >> 5;
    const int wm = wid & 3, wn = wid >> 2;
    const int m0 = blockIdx.y * 128;
    const int n0 = blockIdx.x * 128;

    const char* gA = (const char*)A + (size_t)m0 * (KEXT * 2);
    const char* gB = (const char*)Bm + (size_t)n0 * 2;   // row k stride = NTOT*2

    // A-chunk coords: 32 rows x 8 chunks
    const int arow = tid >> 3;
    const int acol = (tid & 7) * 16;
    // B-chunk coords: 16 k-rows x 16 chunks (256B of n per k-row)
    const int bk = tid >> 4;          // 0..15, +16 per i
    const int bc = tid & 15;          // chunk: 0..15
    const uint32_t bsub = (uint32_t)(bc >> 3) * 8192u;  // n-subtile 0 or 1
    const uint32_t bcol = (uint32_t)(bc & 7) * 16u;

    auto load_tile = [&](int it, int buf) {
        const uint32_t ao = (uint32_t)buf * STAGE_BYTES;
        const uint32_t bo = ao + 16384u;
        #pragma unroll
        for (int i = 0; i < 4; i++) {
            int r = arow + i * 32;
            CP16(sb + ao + SW128(r * 128 + acol),
                 gA + (size_t)r * (KEXT * 2) + (size_t)it * 128 + acol);
        }
        #pragma unroll
        for (int i = 0; i < 4; i++) {
            int k = bk + i * 16;
            CP16(sb + bo + bsub + SW128(k * 128 + bcol),
                 gB + ((size_t)(it * 64 + k) * NTOT) * 2 + bc * 16);
        }
    };

    float acc[2][8][4];
    #pragma unroll
    for (int mt = 0; mt < 2; mt++)
        #pragma unroll
        for (int nt = 0; nt < 8; nt++)
            #pragma unroll
            for (int j = 0; j < 4; j++) acc[mt][nt][j] = 0.f;

    load_tile(0, 0); CP_COMMIT();
    load_tile(1, 1); CP_COMMIT();

    int buf = 0;
    for (int it = 0; it < KITERS; it++) {
        CP_WAIT1();
        __syncthreads();
        if (it + 2 < KITERS) load_tile(it + 2, (buf + 2) % 3);
        CP_COMMIT();

        const uint32_t ao = (uint32_t)buf * STAGE_BYTES;
        const uint32_t bo = ao + 16384u + (uint32_t)wn * 8192u;  // this warp's subtile

        #pragma unroll
        for (int ks = 0; ks < 4; ks++) {
            uint32_t a[2][4];
            #pragma unroll
            for (int mt = 0; mt < 2; mt++) {
                uint32_t addr = sb + ao +
                    SW128((wm * 32 + mt * 16 + (lane & 15)) * 128 +
                          ks * 32 + ((lane >> 4) << 4));
                ldsm4(a[mt][0], a[mt][1], a[mt][2], a[mt][3], addr);
            }
            uint32_t b[8][2];
            #pragma unroll
            for (int p = 0; p < 4; p++) {
                // trans load from [k][n] subtile: rows = k, 16B = 8 n values
                uint32_t addr = sb + bo +
                    SW128((ks * 16 + (lane & 15)) * 128 +
                          p * 32 + ((lane >> 4) << 4));
                ldsm4t(b[2 * p][0], b[2 * p][1], b[2 * p + 1][0], b[2 * p + 1][1], addr);
            }
            #pragma unroll
            for (int mt = 0; mt < 2; mt++)
                #pragma unroll
                for (int nt = 0; nt < 8; nt++)
                    mma_f16(acc[mt][nt], a[mt], b[nt][0], b[nt][1]);
        }
        buf = (buf + 1) % 3;
    }

    const int colbase = n0 + wn * 64;
    if (MODE == 0) {
        const int s = colbase >> 10;
        const int h = (colbase >> 6) & 15;
        __half* dst = (s == 0) ? Qh : ((s == 1) ? Kh : Vh);
        const float scl = (s == 0) ? QSCALE : 1.0f;
        #pragma unroll
        for (int mt = 0; mt < 2; mt++) {
            #pragma unroll
            for (int hf = 0; hf < 2; hf++) {
                int r = m0 + wm * 32 + mt * 16 + (lane >> 2) + hf * 8;
                int bidx = r >> 11, n = r & (NSEQ - 1);
                size_t rowoff = (((size_t)bidx * HH + h) * NSEQ + n) * DD;
                #pragma unroll
                for (int nt = 0; nt < 8; nt++) {
                    int dd = nt * 8 + (lane & 3) * 2;
                    float v0 = (acc[mt][nt][hf * 2 + 0] + bias[colbase + dd]) * scl;
                    float v1 = (acc[mt][nt][hf * 2 + 1] + bias[colbase + dd + 1]) * scl;
                    *(__half2*)&dst[rowoff + dd] =
                        __float22half2_rn(make_float2(v0, v1));
                }
            }
        }
    } else {
        #pragma unroll
        for (int mt = 0; mt < 2; mt++) {
            #pragma unroll
            for (int hf = 0; hf < 2; hf++) {
                int r = m0 + wm * 32 + mt * 16 + (lane >> 2) + hf * 8;
                float* crow2 = &Cout[(size_t)r * CC];
                #pragma unroll
                for (int nt = 0; nt < 8; nt++) {
                    int cc = colbase + nt * 8 + (lane & 3) * 2;
                    float2 o;
                    o.x = acc[mt][nt][hf * 2 + 0] + bias[cc];
                    o.y = acc[mt][nt][hf * 2 + 1] + bias[cc + 1];
                    *(float2*)&crow2[cc] = o;
                }
            }
        }
    }
}

// ---------------------------------------------------------------------------
// Flash attention — R8 variant verbatim: fp16 HMMA, log2 softmax, 3-stage KV
// pipeline, Q hoisted, rowsum via ones-MMA, V via ldsm4t, rescale skip.
// 2 CTAs/SM.
// ---------------------------------------------------------------------------
#define FL_SQ 0u
#define FL_KV(buf) (16384u + (uint32_t)(buf) * 16384u)
#define FL_SMEM (65536 + 128)
#define NKB (NSEQ / 64)
#define ONES2 0x3C003C00u

__global__ __launch_bounds__(256, 2) void flash_mma_kernel(
    const __half* __restrict__ Qh, const __half* __restrict__ Kh,
    const __half* __restrict__ Vh, __half* __restrict__ Oh)
{
    extern __shared__ char smraw[];
    char* smp = (char*)(((uintptr_t)smraw + 127) & ~(uintptr_t)127);
    const uint32_t sb = smem_u32(smp);

    const int tid = threadIdx.x;
    const int lane = tid & 31, w = tid >> 5;
    const int bh = blockIdx.y;
    const int q0 = blockIdx.x * 128;
    const size_t base = (size_t)bh * NSEQ * DD;

    const char* gK = (const char*)(Kh + base);
    const char* gV = (const char*)(Vh + base);
    const int crow = tid >> 3;
    const int ccol = (tid & 7) * 16;

    auto load_kv = [&](int kc, int buf) {
        const size_t rb = (size_t)kc * 64 * 128;
        const uint32_t ko = FL_KV(buf), vo = ko + 8192u;
        #pragma unroll
        for (int i = 0; i < 2; i++) {
            int r = crow + i * 32;
            CP16(sb + ko + SW128(r * 128 + ccol), gK + rb + (size_t)r * 128 + ccol);
        }
        #pragma unroll
        for (int i = 0; i < 2; i++) {
            int r = crow + i * 32;
            CP16(sb + vo + SW128(r * 128 + ccol), gV + rb + (size_t)r * 128 + ccol);
        }
    };

    {
        const char* gQ = (const char*)(Qh + base + (size_t)q0 * DD);
        #pragma unroll
        for (int i = 0; i < 4; i++) {
            int r = crow + i * 32;
            CP16(sb + FL_SQ + SW128(r * 128 + ccol), gQ + (size_t)r * 128 + ccol);
        }
    }
    load_kv(0, 0); CP_COMMIT();
    load_kv(1, 1); CP_COMMIT();

    uint32_t qf[4][4];
    float oacc[8][4];
    #pragma unroll
    for (int nt = 0; nt < 8; nt++)
        #pragma unroll
        for (int j = 0; j < 4; j++) oacc[nt][j] = 0.f;
    float m0r = -1e30f, m1r = -1e30f, l0r = 0.f, l1r = 0.f;

    int buf = 0;
    for (int kc = 0; kc < NKB; kc++) {
        CP_WAIT1();
        __syncthreads();
        if (kc + 2 < NKB) load_kv(kc + 2, (buf + 2) % 3);
        CP_COMMIT();

        if (kc == 0) {
            #pragma unroll
            for (int ks = 0; ks < 4; ks++)
                ldsm4(qf[ks][0], qf[ks][1], qf[ks][2], qf[ks][3],
                      sb + FL_SQ + SW128((w * 16 + (lane & 15)) * 128 +
                                         ks * 32 + ((lane >> 4) << 4)));
        }
        const uint32_t ko = FL_KV(buf), vo = ko + 8192u;

        float sacc[8][4];
        #pragma unroll
        for (int nt = 0; nt < 8; nt++)
            #pragma unroll
            for (int j = 0; j < 4; j++) sacc[nt][j] = 0.f;

        #pragma unroll
        for (int ks = 0; ks < 4; ks++) {
            #pragma unroll
            for (int p = 0; p < 4; p++) {
                uint32_t b0, b1, b2, b3;
                ldsm4(b0, b1, b2, b3,
                      sb + ko + SW128((p * 16 + (lane & 7) + ((lane >> 4) & 1) * 8) * 128 +
                                      ks * 32 + ((lane >> 3) & 1) * 16));
                mma_f16(sacc[2 * p], qf[ks], b0, b1);
                mma_f16(sacc[2 * p + 1], qf[ks], b2, b3);
            }
        }

        float mx0 = m0r, mx1 = m1r;
        #pragma unroll
        for (int nt = 0; nt < 8; nt++) {
            mx0 = fmaxf(mx0, fmaxf(sacc[nt][0], sacc[nt][1]));
            mx1 = fmaxf(mx1, fmaxf(sacc[nt][2], sacc[nt][3]));
        }
        mx0 = fmaxf(mx0, __shfl_xor_sync(0xffffffffu, mx0, 1));
        mx0 = fmaxf(mx0, __shfl_xor_sync(0xffffffffu, mx0, 2));
        mx1 = fmaxf(mx1, __shfl_xor_sync(0xffffffffu, mx1, 1));
        mx1 = fmaxf(mx1, __shfl_xor_sync(0xffffffffu, mx1, 2));

        float alpha0 = ex2_f32(m0r - mx0);
        float alpha1 = ex2_f32(m1r - mx1);
        m0r = mx0; m1r = mx1;

        if (__any_sync(0xffffffffu, (alpha0 != 1.f) || (alpha1 != 1.f))) {
            #pragma unroll
            for (int nt = 0; nt < 8; nt++) {
                oacc[nt][0] *= alpha0; oacc[nt][1] *= alpha0;
                oacc[nt][2] *= alpha1; oacc[nt][3] *= alpha1;
            }
        }

        float ssum[4] = {0.f, 0.f, 0.f, 0.f};
        #pragma unroll
        for (int kt = 0; kt < 4; kt++) {
            uint32_t pa[4];
            pa[0] = ex2_h2(pack_h2(sacc[2 * kt][0] - mx0,     sacc[2 * kt][1] - mx0));
            pa[1] = ex2_h2(pack_h2(sacc[2 * kt][2] - mx1,     sacc[2 * kt][3] - mx1));
            pa[2] = ex2_h2(pack_h2(sacc[2 * kt + 1][0] - mx0, sacc[2 * kt + 1][1] - mx0));
            pa[3] = ex2_h2(pack_h2(sacc[2 * kt + 1][2] - mx1, sacc[2 * kt + 1][3] - mx1));
            mma_f16(ssum, pa, ONES2, ONES2);
            #pragma unroll
            for (int ntp = 0; ntp < 4; ntp++) {
                uint32_t v0, v1, v2, v3;
                ldsm4t(v0, v1, v2, v3,
                       sb + vo + SW128((kt * 16 + (lane & 15)) * 128 +
                                       ntp * 32 + ((lane >> 4) << 4)));
                mma_f16(oacc[2 * ntp],     pa, v0, v1);
                mma_f16(oacc[2 * ntp + 1], pa, v2, v3);
            }
        }
        l0r = l0r * alpha0 + ssum[0];
        l1r = l1r * alpha1 + ssum[2];

        buf = (buf + 1) % 3;
    }

    const float inv0 = 1.f / l0r, inv1 = 1.f / l1r;
    const int b = bh >> 4, h = bh & 15;
    #pragma unroll
    for (int hf = 0; hf < 2; hf++) {
        int n = q0 + w * 16 + (lane >> 2) + hf * 8;
        float inv = hf ? inv1 : inv0;
        __half* orow = Oh + ((size_t)b * NSEQ + n) * CC;
        #pragma unroll
        for (int nt = 0; nt < 8; nt++) {
            int col = h * 64 + nt * 8 + (lane & 3) * 2;
            float o0 = oacc[nt][hf * 2 + 0] * inv;
            float o1 = oacc[nt][hf * 2 + 1] * inv;
            *(__half2*)&orow[col] = __float22half2_rn(make_float2(o0, o1));
        }
    }
}

// ---------------------------------------------------------------------------
// Launcher
// ---------------------------------------------------------------------------
extern "C" void kernel_launch(void* const* d_in, const int* in_sizes, int n_in,
                              void* d_out, int out_size)
{
    const float* x     = (const float*)d_in[0];
    const float* W_qkv = (const float*)d_in[1];
    const float* b_qkv = (const float*)d_in[2];
    const float* W_out = (const float*)d_in[3];
    const float* b_out = (const float*)d_in[4];
    float* out = (float*)d_out;

    __half *qh, *kh, *vh, *xh, *Oh, *Bq, *Bo;
    cudaGetSymbolAddress((void**)&qh, g_qh);
    cudaGetSymbolAddress((void**)&kh, g_kh);
    cudaGetSymbolAddress((void**)&vh, g_vh);
    cudaGetSymbolAddress((void**)&xh, g_xh);
    cudaGetSymbolAddress((void**)&Oh, g_Oh);
    cudaGetSymbolAddress((void**)&Bq, g_Bq);
    cudaGetSymbolAddress((void**)&Bo, g_Bo);

    cudaFuncSetAttribute((const void*)mma_gemm_kernel<0>,
                         cudaFuncAttributeMaxDynamicSharedMemorySize, GEMM_SMEM);
    cudaFuncSetAttribute((const void*)mma_gemm_kernel<1>,
                         cudaFuncAttributeMaxDynamicSharedMemorySize, GEMM_SMEM);
    cudaFuncSetAttribute(flash_mma_kernel,
                         cudaFuncAttributeMaxDynamicSharedMemorySize, FL_SMEM);

    // 1) fused prep: elementwise casts only (x, W_qkv, W_out)
    prep_kernel<<<NB_X + NB_WQ + NB_WO, 256>>>(x, W_qkv, W_out, xh, Bq, Bo);
    // 2) QKV projection (HMMA fp16, B natural layout) -> fp16 Q(scaled)/K/V
    mma_gemm_kernel<0><<<dim3(K3 / 128, MM / 128), 256, GEMM_SMEM>>>(
        xh, Bq, b_qkv, nullptr, qh, kh, vh);
    // 3) Flash attention (R8 variant) -> Oh [B,N,C] fp16
    flash_mma_kernel<<<dim3(NSEQ / 128, BB * HH), 256, FL_SMEM>>>(qh, kh, vh, Oh);
    // 4) Output projection -> out
    mma_gemm_kernel<1><<<dim3(CC / 128, MM / 128), 256, GEMM_SMEM>>>(
        Oh, Bo, b_out, out, nullptr, nullptr, nullptr);
}

// round 14
// speedup vs baseline: 1.6064x; 1.0278x over previous
#include <cuda_runtime.h>
#include <cuda_fp16.h>
#include <math.h>
#include <stdint.h>

#define BB 2
#define HH 16
#define NSEQ 2048
#define DD 64
#define CC 1024
#define MM (BB*NSEQ)      /* 4096 */
#define K3 (3*CC)         /* 3072 */

// ---------------------------------------------------------------------------
// Scratch (__device__ globals; allocation-free rule)
// ---------------------------------------------------------------------------
__device__ __align__(256) __half g_qh[(size_t)BB*HH*NSEQ*DD];   // Q fp16, pre-scaled 0.125*log2e
__device__ __align__(256) __half g_kh[(size_t)BB*HH*NSEQ*DD];
__device__ __align__(256) __half g_vh[(size_t)BB*HH*NSEQ*DD];
__device__ __align__(256) __half g_xh[(size_t)MM*CC];           // x cast to fp16
__device__ __align__(256) __half g_Oh[(size_t)MM*CC];           // attention out, fp16
__device__ __align__(256) __half g_Bq[(size_t)K3*CC];           // W_qkv fp16 K-major
__device__ __align__(256) __half g_Bo[(size_t)CC*CC];           // W_out fp16 K-major

// ---------------------------------------------------------------------------
// PTX helpers (baseline sm_80 ISA — safe on plain sm_103 target)
// ---------------------------------------------------------------------------
__device__ __forceinline__ uint32_t smem_u32(const void* p) {
    uint32_t a;
    asm("{ .reg .u64 t; cvta.to.shared.u64 t, %1; cvt.u32.u64 %0, t; }"
        : "=r"(a) : "l"(p));
    return a;
}

#define SW128(off) ((off) ^ (((off) >> 3) & 0x70))

#define CP16(dst, src) \
    asm volatile("cp.async.cg.shared.global [%0], [%1], 16;" :: "r"(dst), "l"(src))
#define CP_COMMIT() asm volatile("cp.async.commit_group;" ::: "memory")
#define CP_WAIT1()  asm volatile("cp.async.wait_group 1;" ::: "memory")

__device__ __forceinline__ void ldsm4(uint32_t& r0, uint32_t& r1,
                                      uint32_t& r2, uint32_t& r3, uint32_t a) {
    asm volatile("ldmatrix.sync.aligned.m8n8.x4.shared.b16 {%0,%1,%2,%3}, [%4];"
        : "=r"(r0), "=r"(r1), "=r"(r2), "=r"(r3) : "r"(a));
}
__device__ __forceinline__ void ldsm4t(uint32_t& r0, uint32_t& r1,
                                       uint32_t& r2, uint32_t& r3, uint32_t a) {
    asm volatile("ldmatrix.sync.aligned.m8n8.x4.trans.shared.b16 {%0,%1,%2,%3}, [%4];"
        : "=r"(r0), "=r"(r1), "=r"(r2), "=r"(r3) : "r"(a));
}
__device__ __forceinline__ void mma_f16(float* c, const uint32_t* a, uint32_t b0, uint32_t b1) {
    asm volatile("mma.sync.aligned.m16n8k16.row.col.f32.f16.f16.f32 "
        "{%0,%1,%2,%3}, {%4,%5,%6,%7}, {%8,%9}, {%0,%1,%2,%3};"
        : "+f"(c[0]), "+f"(c[1]), "+f"(c[2]), "+f"(c[3])
        : "r"(a[0]), "r"(a[1]), "r"(a[2]), "r"(a[3]), "r"(b0), "r"(b1));
}

__device__ __forceinline__ uint32_t pack_h2(float lo, float hi) {
    __half2 h = __float22half2_rn(make_float2(lo, hi));
    return *(uint32_t*)&h;
}
__device__ __forceinline__ uint32_t ex2_h2(uint32_t x) {
    uint32_t r;
    asm("ex2.approx.f16x2 %0, %1;" : "=r"(r) : "r"(x));
    return r;
}
__device__ __forceinline__ float ex2_f32(float x) {
    float r;
    asm("ex2.approx.f32 %0, %1;" : "=f"(r) : "f"(x));
    return r;
}

// ---------------------------------------------------------------------------
// Fused prep: cast x->fp16, transpose+cast both weight matrices (K-major).
// ---------------------------------------------------------------------------
#define NB_CAST (MM * CC / 1024)          /* 4096 */
#define NB_TQ   ((CC / 32) * (K3 / 32))   /* 3072 */
#define NB_TO   ((CC / 32) * (CC / 32))   /* 1024 */

__global__ __launch_bounds__(256) void prep_kernel(
    const float* __restrict__ x,  const float* __restrict__ Wq,
    const float* __restrict__ Wo, __half* __restrict__ xh,
    __half* __restrict__ Bq, __half* __restrict__ Bo)
{
    const int bid = blockIdx.x, tid = threadIdx.x;
    if (bid < NB_CAST) {
        size_t idx4 = ((size_t)bid * 256 + tid) * 4;
        float4 v = *(const float4*)&x[idx4];
        __half2 a = __float22half2_rn(make_float2(v.x, v.y));
        __half2 b = __float22half2_rn(make_float2(v.z, v.w));
        *(uint2*)&xh[idx4] = make_uint2(*(uint32_t*)&a, *(uint32_t*)&b);
        return;
    }
    const float* W; __half* Bd; int N, b;
    if (bid < NB_CAST + NB_TQ) { b = bid - NB_CAST; W = Wq; Bd = Bq; N = K3; }
    else                       { b = bid - NB_CAST - NB_TQ; W = Wo; Bd = Bo; N = CC; }
    const int k0 = (b % 32) * 32;
    const int n0 = (b / 32) * 32;
    const int tx = tid & 31, ty = tid >> 5;

    __shared__ float t[32][33];
    #pragma unroll
    for (int i = 0; i < 4; i++)
        t[ty + i * 8][tx] = W[(size_t)(k0 + ty + i * 8) * N + n0 + tx];
    __syncthreads();
    #pragma unroll
    for (int i = 0; i < 4; i++) {
        int n = n0 + ty + i * 8, k = k0 + tx;
        Bd[(size_t)n * CC + k] = __float2half_rn(t[tx][ty + i * 8]);
    }
}

// ---------------------------------------------------------------------------
// HMMA GEMM: D[M][N] = A[M][1024] @ B[N][1024]^T (+bias)   (R8 verbatim)
// BM=128, BN=128, BK=64, 3-stage cp.async, 1 sync/iter, 2 CTAs/SM.
// ---------------------------------------------------------------------------
#define STAGE_BYTES 32768
#define GEMM_SMEM (3 * STAGE_BYTES + 128)
#define KEXT 1024
#define KITERS (KEXT / 64)
#define QSCALE 0.18033688f   /* 0.125 * log2(e) */

template<int MODE>
__global__ __launch_bounds__(256, 2) void mma_gemm_kernel(
    const __half* __restrict__ A,
    const __half* __restrict__ Bm,
    const float* __restrict__ bias,
    float* __restrict__ Cout,
    __half* __restrict__ Qh, __half* __restrict__ Kh, __half* __restrict__ Vh)
{
    extern __shared__ char smraw[];
    char* smp = (char*)(((uintptr_t)smraw + 127) & ~(uintptr_t)127);
    const uint32_t sb = smem_u32(smp);

    const int tid = threadIdx.x;
    const int lane = tid & 31, wid = tid >> 5;
    const int wm = wid & 3, wn = wid >> 2;
    const int m0 = blockIdx.y * 128;
    const int n0 = blockIdx.x * 128;

    const char* gA = (const char*)A + (size_t)m0 * (KEXT * 2);
    const char* gB = (const char*)Bm + (size_t)n0 * (KEXT * 2);

    const int crow = tid >> 3;
    const int ccol = (tid & 7) * 16;

    auto load_tile = [&](int it, int buf) {
        const uint32_t ao = (uint32_t)buf * STAGE_BYTES;
        const uint32_t bo = ao + 16384u;
        const size_t kbyte = (size_t)it * 128;
        #pragma unroll
        for (int i = 0; i < 4; i++) {
            int r = crow + i * 32;
            CP16(sb + ao + SW128(r * 128 + ccol),
                 gA + (size_t)r * (KEXT * 2) + kbyte + ccol);
        }
        #pragma unroll
        for (int i = 0; i < 4; i++) {
            int r = crow + i * 32;
            CP16(sb + bo + SW128(r * 128 + ccol),
                 gB + (size_t)r * (KEXT * 2) + kbyte + ccol);
        }
    };

    float acc[2][8][4];
    #pragma unroll
    for (int mt = 0; mt < 2; mt++)
        #pragma unroll
        for (int nt = 0; nt < 8; nt++)
            #pragma unroll
            for (int j = 0; j < 4; j++) acc[mt][nt][j] = 0.f;

    load_tile(0, 0); CP_COMMIT();
    load_tile(1, 1); CP_COMMIT();

    int buf = 0;
    for (int it = 0; it < KITERS; it++) {
        CP_WAIT1();
        __syncthreads();
        if (it + 2 < KITERS) load_tile(it + 2, (buf + 2) % 3);
        CP_COMMIT();

        const uint32_t ao = (uint32_t)buf * STAGE_BYTES;
        const uint32_t bo = ao + 16384u;

        #pragma unroll
        for (int ks = 0; ks < 4; ks++) {
            uint32_t a[2][4];
            #pragma unroll
            for (int mt = 0; mt < 2; mt++) {
                uint32_t addr = sb + ao +
                    SW128((wm * 32 + mt * 16 + (lane & 15)) * 128 +
                          ks * 32 + ((lane >> 4) << 4));
                ldsm4(a[mt][0], a[mt][1], a[mt][2], a[mt][3], addr);
            }
            uint32_t b[8][2];
            #pragma unroll
            for (int p = 0; p < 4; p++) {
                uint32_t addr = sb + bo +
                    SW128((wn * 64 + p * 16 + (lane & 7) + ((lane >> 4) & 1) * 8) * 128 +
                          ks * 32 + ((lane >> 3) & 1) * 16);
                ldsm4(b[2 * p][0], b[2 * p][1], b[2 * p + 1][0], b[2 * p + 1][1], addr);
            }
            #pragma unroll
            for (int mt = 0; mt < 2; mt++)
                #pragma unroll
                for (int nt = 0; nt < 8; nt++)
                    mma_f16(acc[mt][nt], a[mt], b[nt][0], b[nt][1]);
        }
        buf = (buf + 1) % 3;
    }

    const int colbase = n0 + wn * 64;
    if (MODE == 0) {
        const int s = colbase >> 10;
        const int h = (colbase >> 6) & 15;
        __half* dst = (s == 0) ? Qh : ((s == 1) ? Kh : Vh);
        const float scl = (s == 0) ? QSCALE : 1.0f;
        #pragma unroll
        for (int mt = 0; mt < 2; mt++) {
            #pragma unroll
            for (int hf = 0; hf < 2; hf++) {
                int r = m0 + wm * 32 + mt * 16 + (lane >> 2) + hf * 8;
                int bidx = r >> 11, n = r & (NSEQ - 1);
                size_t rowoff = (((size_t)bidx * HH + h) * NSEQ + n) * DD;
                #pragma unroll
                for (int nt = 0; nt < 8; nt++) {
                    int dd = nt * 8 + (lane & 3) * 2;
                    float v0 = (acc[mt][nt][hf * 2 + 0] + bias[colbase + dd]) * scl;
                    float v1 = (acc[mt][nt][hf * 2 + 1] + bias[colbase + dd + 1]) * scl;
                    *(__half2*)&dst[rowoff + dd] =
                        __float22half2_rn(make_float2(v0, v1));
                }
            }
        }
    } else {
        #pragma unroll
        for (int mt = 0; mt < 2; mt++) {
            #pragma unroll
            for (int hf = 0; hf < 2; hf++) {
                int r = m0 + wm * 32 + mt * 16 + (lane >> 2) + hf * 8;
                float* crow2 = &Cout[(size_t)r * CC];
                #pragma unroll
                for (int nt = 0; nt < 8; nt++) {
                    int cc = colbase + nt * 8 + (lane & 3) * 2;
                    float2 o;
                    o.x = acc[mt][nt][hf * 2 + 0] + bias[cc];
                    o.y = acc[mt][nt][hf * 2 + 1] + bias[cc + 1];
                    *(float2*)&crow2[cc] = o;
                }
            }
        }
    }
}

// ---------------------------------------------------------------------------
// Flash attention — R8 variant + 4-stage KV ring + barrier every 2 iters.
// fp16 HMMA, log2 softmax, Q hoisted, rowsum via ones-MMA, V via ldsm4t,
// rescale skip. 2 CTAs/SM (smem 80KB + Q: 16+64=80KB -> 160KB/SM).
// Hazards (prefetch distance 2, ring of 4):
//   WAR: write@kc hits slot read@kc-2; barrier at every even kc lies in
//        (kc-2, kc] for both parities.
//   RAW: data read@kc completed by each writer's wait_group(1)@kc-1; a
//        barrier separates that from the read for both parities.
// ---------------------------------------------------------------------------
#define FL_SQ 0u
#define FL_KV(buf) (16384u + (uint32_t)(buf) * 16384u)   /* K 8KB then V 8KB */
#define FL_SMEM (16384 + 4 * 16384 + 128)
#define NKB (NSEQ / 64)
#define ONES2 0x3C003C00u

__global__ __launch_bounds__(256, 2) void flash_mma_kernel(
    const __half* __restrict__ Qh, const __half* __restrict__ Kh,
    const __half* __restrict__ Vh, __half* __restrict__ Oh)
{
    extern __shared__ char smraw[];
    char* smp = (char*)(((uintptr_t)smraw + 127) & ~(uintptr_t)127);
    const uint32_t sb = smem_u32(smp);

    const int tid = threadIdx.x;
    const int lane = tid & 31, w = tid >> 5;
    const int bh = blockIdx.y;
    const int q0 = blockIdx.x * 128;
    const size_t base = (size_t)bh * NSEQ * DD;

    const char* gK = (const char*)(Kh + base);
    const char* gV = (const char*)(Vh + base);
    const int crow = tid >> 3;
    const int ccol = (tid & 7) * 16;

    auto load_kv = [&](int kc, int buf) {
        const size_t rb = (size_t)kc * 64 * 128;
        const uint32_t ko = FL_KV(buf), vo = ko + 8192u;
        #pragma unroll
        for (int i = 0; i < 2; i++) {
            int r = crow + i * 32;
            CP16(sb + ko + SW128(r * 128 + ccol), gK + rb + (size_t)r * 128 + ccol);
        }
        #pragma unroll
        for (int i = 0; i < 2; i++) {
            int r = crow + i * 32;
            CP16(sb + vo + SW128(r * 128 + ccol), gV + rb + (size_t)r * 128 + ccol);
        }
    };

    {
        const char* gQ = (const char*)(Qh + base + (size_t)q0 * DD);
        #pragma unroll
        for (int i = 0; i < 4; i++) {
            int r = crow + i * 32;
            CP16(sb + FL_SQ + SW128(r * 128 + ccol), gQ + (size_t)r * 128 + ccol);
        }
    }
    load_kv(0, 0); CP_COMMIT();
    load_kv(1, 1); CP_COMMIT();

    uint32_t qf[4][4];
    float oacc[8][4];
    #pragma unroll
    for (int nt = 0; nt < 8; nt++)
        #pragma unroll
        for (int j = 0; j < 4; j++) oacc[nt][j] = 0.f;
    float m0r = -1e30f, m1r = -1e30f, l0r = 0.f, l1r = 0.f;

    int buf = 0;
    for (int kc = 0; kc < NKB; kc++) {
        CP_WAIT1();
        if ((kc & 1) == 0) __syncthreads();
        if (kc + 2 < NKB) load_kv(kc + 2, (buf + 2) & 3);
        CP_COMMIT();

        if (kc == 0) {
            #pragma unroll
            for (int ks = 0; ks < 4; ks++)
                ldsm4(qf[ks][0], qf[ks][1], qf[ks][2], qf[ks][3],
                      sb + FL_SQ + SW128((w * 16 + (lane & 15)) * 128 +
                                         ks * 32 + ((lane >> 4) << 4)));
        }
        const uint32_t ko = FL_KV(buf), vo = ko + 8192u;

        float sacc[8][4];
        #pragma unroll
        for (int nt = 0; nt < 8; nt++)
            #pragma unroll
            for (int j = 0; j < 4; j++) sacc[nt][j] = 0.f;

        #pragma unroll
        for (int ks = 0; ks < 4; ks++) {
            #pragma unroll
            for (int p = 0; p < 4; p++) {
                uint32_t b0, b1, b2, b3;
                ldsm4(b0, b1, b2, b3,
                      sb + ko + SW128((p * 16 + (lane & 7) + ((lane >> 4) & 1) * 8) * 128 +
                                      ks * 32 + ((lane >> 3) & 1) * 16));
                mma_f16(sacc[2 * p], qf[ks], b0, b1);
                mma_f16(sacc[2 * p + 1], qf[ks], b2, b3);
            }
        }

        float mx0 = m0r, mx1 = m1r;
        #pragma unroll
        for (int nt = 0; nt < 8; nt++) {
            mx0 = fmaxf(mx0, fmaxf(sacc[nt][0], sacc[nt][1]));
            mx1 = fmaxf(mx1, fmaxf(sacc[nt][2], sacc[nt][3]));
        }
        mx0 = fmaxf(mx0, __shfl_xor_sync(0xffffffffu, mx0, 1));
        mx0 = fmaxf(mx0, __shfl_xor_sync(0xffffffffu, mx0, 2));
        mx1 = fmaxf(mx1, __shfl_xor_sync(0xffffffffu, mx1, 1));
        mx1 = fmaxf(mx1, __shfl_xor_sync(0xffffffffu, mx1, 2));

        float alpha0 = ex2_f32(m0r - mx0);
        float alpha1 = ex2_f32(m1r - mx1);
        m0r = mx0; m1r = mx1;

        if (__any_sync(0xffffffffu, (alpha0 != 1.f) || (alpha1 != 1.f))) {
            #pragma unroll
            for (int nt = 0; nt < 8; nt++) {
                oacc[nt][0] *= alpha0; oacc[nt][1] *= alpha0;
                oacc[nt][2] *= alpha1; oacc[nt][3] *= alpha1;
            }
        }

        float ssum[4] = {0.f, 0.f, 0.f, 0.f};
        #pragma unroll
        for (int kt = 0; kt < 4; kt++) {
            uint32_t pa[4];
            pa[0] = ex2_h2(pack_h2(sacc[2 * kt][0] - mx0,     sacc[2 * kt][1] - mx0));
            pa[1] = ex2_h2(pack_h2(sacc[2 * kt][2] - mx1,     sacc[2 * kt][3] - mx1));
            pa[2] = ex2_h2(pack_h2(sacc[2 * kt + 1][0] - mx0, sacc[2 * kt + 1][1] - mx0));
            pa[3] = ex2_h2(pack_h2(sacc[2 * kt + 1][2] - mx1, sacc[2 * kt + 1][3] - mx1));
            mma_f16(ssum, pa, ONES2, ONES2);
            #pragma unroll
            for (int ntp = 0; ntp < 4; ntp++) {
                uint32_t v0, v1, v2, v3;
                ldsm4t(v0, v1, v2, v3,
                       sb + vo + SW128((kt * 16 + (lane & 15)) * 128 +
                                       ntp * 32 + ((lane >> 4) << 4)));
                mma_f16(oacc[2 * ntp],     pa, v0, v1);
                mma_f16(oacc[2 * ntp + 1], pa, v2, v3);
            }
        }
        l0r = l0r * alpha0 + ssum[0];
        l1r = l1r * alpha1 + ssum[2];

        buf = (buf + 1) & 3;
    }

    const float inv0 = 1.f / l0r, inv1 = 1.f / l1r;
    const int b = bh >> 4, h = bh & 15;
    #pragma unroll
    for (int hf = 0; hf < 2; hf++) {
        int n = q0 + w * 16 + (lane >> 2) + hf * 8;
        float inv = hf ? inv1 : inv0;
        __half* orow = Oh + ((size_t)b * NSEQ + n) * CC;
        #pragma unroll
        for (int nt = 0; nt < 8; nt++) {
            int col = h * 64 + nt * 8 + (lane & 3) * 2;
            float o0 = oacc[nt][hf * 2 + 0] * inv;
            float o1 = oacc[nt][hf * 2 + 1] * inv;
            *(__half2*)&orow[col] = __float22half2_rn(make_float2(o0, o1));
        }
    }
}

// ---------------------------------------------------------------------------
// Launcher
// ---------------------------------------------------------------------------
extern "C" void kernel_launch(void* const* d_in, const int* in_sizes, int n_in,
                              void* d_out, int out_size)
{
    const float* x     = (const float*)d_in[0];
    const float* W_qkv = (const float*)d_in[1];
    const float* b_qkv = (const float*)d_in[2];
    const float* W_out = (const float*)d_in[3];
    const float* b_out = (const float*)d_in[4];
    float* out = (float*)d_out;

    __half *qh, *kh, *vh, *xh, *Oh, *Bq, *Bo;
    cudaGetSymbolAddress((void**)&qh, g_qh);
    cudaGetSymbolAddress((void**)&kh, g_kh);
    cudaGetSymbolAddress((void**)&vh, g_vh);
    cudaGetSymbolAddress((void**)&xh, g_xh);
    cudaGetSymbolAddress((void**)&Oh, g_Oh);
    cudaGetSymbolAddress((void**)&Bq, g_Bq);
    cudaGetSymbolAddress((void**)&Bo, g_Bo);

    cudaFuncSetAttribute((const void*)mma_gemm_kernel<0>,
                         cudaFuncAttributeMaxDynamicSharedMemorySize, GEMM_SMEM);
    cudaFuncSetAttribute((const void*)mma_gemm_kernel<1>,
                         cudaFuncAttributeMaxDynamicSharedMemorySize, GEMM_SMEM);
    cudaFuncSetAttribute(flash_mma_kernel,
                         cudaFuncAttributeMaxDynamicSharedMemorySize, FL_SMEM);

    // 1) fused prep: cast x; transpose+cast W_qkv, W_out (K-major)
    prep_kernel<<<NB_CAST + NB_TQ + NB_TO, 256>>>(x, W_qkv, W_out, xh, Bq, Bo);
    // 2) QKV projection (HMMA fp16, K=1024) -> fp16 Q(log2-scaled)/K/V
    mma_gemm_kernel<0><<<dim3(K3 / 128, MM / 128), 256, GEMM_SMEM>>>(
        xh, Bq, b_qkv, nullptr, qh, kh, vh);
    // 3) Flash attention (4-stage ring, barrier/2 iters) -> Oh [B,N,C] fp16
    flash_mma_kernel<<<dim3(NSEQ / 128, BB * HH), 256, FL_SMEM>>>(qh, kh, vh, Oh);
    // 4) Output projection -> out
    mma_gemm_kernel<1><<<dim3(CC / 128, MM / 128), 256, GEMM_SMEM>>>(
        Oh, Bo, b_out, out, nullptr, nullptr, nullptr);
}

// round 15
// speedup vs baseline: 1.6292x; 1.0142x over previous
#include <cuda_runtime.h>
#include <cuda_fp16.h>
#include <math.h>
#include <stdint.h>

#define BB 2
#define HH 16
#define NSEQ 2048
#define DD 64
#define CC 1024
#define MM (BB*NSEQ)      /* 4096 */
#define K3 (3*CC)         /* 3072 */

// ---------------------------------------------------------------------------
// Scratch (__device__ globals; allocation-free rule)
// ---------------------------------------------------------------------------
__device__ __align__(256) __half g_qh[(size_t)BB*HH*NSEQ*DD];   // Q fp16, pre-scaled 0.125*log2e
__device__ __align__(256) __half g_kh[(size_t)BB*HH*NSEQ*DD];
__device__ __align__(256) __half g_vh[(size_t)BB*HH*NSEQ*DD];
__device__ __align__(256) __half g_xh[(size_t)MM*CC];           // x cast to fp16
__device__ __align__(256) __half g_Oh[(size_t)MM*CC];           // attention out, fp16
__device__ __align__(256) __half g_Bq[(size_t)K3*CC];           // W_qkv fp16 K-major
__device__ __align__(256) __half g_Bo[(size_t)CC*CC];           // W_out fp16 K-major

// ---------------------------------------------------------------------------
// PTX helpers (baseline sm_80 ISA — safe on plain sm_103 target)
// ---------------------------------------------------------------------------
__device__ __forceinline__ uint32_t smem_u32(const void* p) {
    uint32_t a;
    asm("{ .reg .u64 t; cvta.to.shared.u64 t, %1; cvt.u32.u64 %0, t; }"
        : "=r"(a) : "l"(p));
    return a;
}

#define SW128(off) ((off) ^ (((off) >> 3) & 0x70))

#define CP16(dst, src) \
    asm volatile("cp.async.cg.shared.global [%0], [%1], 16;" :: "r"(dst), "l"(src))
#define CP_COMMIT() asm volatile("cp.async.commit_group;" ::: "memory")
#define CP_WAIT1()  asm volatile("cp.async.wait_group 1;" ::: "memory")

__device__ __forceinline__ void ldsm4(uint32_t& r0, uint32_t& r1,
                                      uint32_t& r2, uint32_t& r3, uint32_t a) {
    asm volatile("ldmatrix.sync.aligned.m8n8.x4.shared.b16 {%0,%1,%2,%3}, [%4];"
        : "=r"(r0), "=r"(r1), "=r"(r2), "=r"(r3) : "r"(a));
}
__device__ __forceinline__ void ldsm4t(uint32_t& r0, uint32_t& r1,
                                       uint32_t& r2, uint32_t& r3, uint32_t a) {
    asm volatile("ldmatrix.sync.aligned.m8n8.x4.trans.shared.b16 {%0,%1,%2,%3}, [%4];"
        : "=r"(r0), "=r"(r1), "=r"(r2), "=r"(r3) : "r"(a));
}
__device__ __forceinline__ void mma_f16(float* c, const uint32_t* a, uint32_t b0, uint32_t b1) {
    asm volatile("mma.sync.aligned.m16n8k16.row.col.f32.f16.f16.f32 "
        "{%0,%1,%2,%3}, {%4,%5,%6,%7}, {%8,%9}, {%0,%1,%2,%3};"
        : "+f"(c[0]), "+f"(c[1]), "+f"(c[2]), "+f"(c[3])
        : "r"(a[0]), "r"(a[1]), "r"(a[2]), "r"(a[3]), "r"(b0), "r"(b1));
}

__device__ __forceinline__ uint32_t pack_h2(float lo, float hi) {
    __half2 h = __float22half2_rn(make_float2(lo, hi));
    return *(uint32_t*)&h;
}
__device__ __forceinline__ uint32_t ex2_h2(uint32_t x) {
    uint32_t r;
    asm("ex2.approx.f16x2 %0, %1;" : "=r"(r) : "r"(x));
    return r;
}
__device__ __forceinline__ float ex2_f32(float x) {
    float r;
    asm("ex2.approx.f32 %0, %1;" : "=f"(r) : "f"(x));
    return r;
}

// ---------------------------------------------------------------------------
// Fused prep: cast x->fp16, transpose+cast both weight matrices (K-major).
// ---------------------------------------------------------------------------
#define NB_CAST (MM * CC / 1024)          /* 4096 */
#define NB_TQ   ((CC / 32) * (K3 / 32))   /* 3072 */
#define NB_TO   ((CC / 32) * (CC / 32))   /* 1024 */

__global__ __launch_bounds__(256) void prep_kernel(
    const float* __restrict__ x,  const float* __restrict__ Wq,
    const float* __restrict__ Wo, __half* __restrict__ xh,
    __half* __restrict__ Bq, __half* __restrict__ Bo)
{
    const int bid = blockIdx.x, tid = threadIdx.x;
    if (bid < NB_CAST) {
        size_t idx4 = ((size_t)bid * 256 + tid) * 4;
        float4 v = *(const float4*)&x[idx4];
        __half2 a = __float22half2_rn(make_float2(v.x, v.y));
        __half2 b = __float22half2_rn(make_float2(v.z, v.w));
        *(uint2*)&xh[idx4] = make_uint2(*(uint32_t*)&a, *(uint32_t*)&b);
        return;
    }
    const float* W; __half* Bd; int N, b;
    if (bid < NB_CAST + NB_TQ) { b = bid - NB_CAST; W = Wq; Bd = Bq; N = K3; }
    else                       { b = bid - NB_CAST - NB_TQ; W = Wo; Bd = Bo; N = CC; }
    const int k0 = (b % 32) * 32;
    const int n0 = (b / 32) * 32;
    const int tx = tid & 31, ty = tid >> 5;

    __shared__ float t[32][33];
    #pragma unroll
    for (int i = 0; i < 4; i++)
        t[ty + i * 8][tx] = W[(size_t)(k0 + ty + i * 8) * N + n0 + tx];
    __syncthreads();
    #pragma unroll
    for (int i = 0; i < 4; i++) {
        int n = n0 + ty + i * 8, k = k0 + tx;
        Bd[(size_t)n * CC + k] = __float2half_rn(t[tx][ty + i * 8]);
    }
}

// ---------------------------------------------------------------------------
// HMMA GEMM: D[M][N] = A[M][1024] @ B[N][1024]^T (+bias)   (R8 verbatim)
// BM=128, BN=128, BK=64, 3-stage cp.async, 1 sync/iter, 2 CTAs/SM.
// ---------------------------------------------------------------------------
#define STAGE_BYTES 32768
#define GEMM_SMEM (3 * STAGE_BYTES + 128)
#define KEXT 1024
#define KITERS (KEXT / 64)
#define QSCALE 0.18033688f   /* 0.125 * log2(e) */

template<int MODE>
__global__ __launch_bounds__(256, 2) void mma_gemm_kernel(
    const __half* __restrict__ A,
    const __half* __restrict__ Bm,
    const float* __restrict__ bias,
    float* __restrict__ Cout,
    __half* __restrict__ Qh, __half* __restrict__ Kh, __half* __restrict__ Vh)
{
    extern __shared__ char smraw[];
    char* smp = (char*)(((uintptr_t)smraw + 127) & ~(uintptr_t)127);
    const uint32_t sb = smem_u32(smp);

    const int tid = threadIdx.x;
    const int lane = tid & 31, wid = tid >> 5;
    const int wm = wid & 3, wn = wid >> 2;
    const int m0 = blockIdx.y * 128;
    const int n0 = blockIdx.x * 128;

    const char* gA = (const char*)A + (size_t)m0 * (KEXT * 2);
    const char* gB = (const char*)Bm + (size_t)n0 * (KEXT * 2);

    const int crow = tid >> 3;
    const int ccol = (tid & 7) * 16;

    auto load_tile = [&](int it, int buf) {
        const uint32_t ao = (uint32_t)buf * STAGE_BYTES;
        const uint32_t bo = ao + 16384u;
        const size_t kbyte = (size_t)it * 128;
        #pragma unroll
        for (int i = 0; i < 4; i++) {
            int r = crow + i * 32;
            CP16(sb + ao + SW128(r * 128 + ccol),
                 gA + (size_t)r * (KEXT * 2) + kbyte + ccol);
        }
        #pragma unroll
        for (int i = 0; i < 4; i++) {
            int r = crow + i * 32;
            CP16(sb + bo + SW128(r * 128 + ccol),
                 gB + (size_t)r * (KEXT * 2) + kbyte + ccol);
        }
    };

    float acc[2][8][4];
    #pragma unroll
    for (int mt = 0; mt < 2; mt++)
        #pragma unroll
        for (int nt = 0; nt < 8; nt++)
            #pragma unroll
            for (int j = 0; j < 4; j++) acc[mt][nt][j] = 0.f;

    load_tile(0, 0); CP_COMMIT();
    load_tile(1, 1); CP_COMMIT();

    int buf = 0;
    for (int it = 0; it < KITERS; it++) {
        CP_WAIT1();
        __syncthreads();
        if (it + 2 < KITERS) load_tile(it + 2, (buf + 2) % 3);
        CP_COMMIT();

        const uint32_t ao = (uint32_t)buf * STAGE_BYTES;
        const uint32_t bo = ao + 16384u;

        #pragma unroll
        for (int ks = 0; ks < 4; ks++) {
            uint32_t a[2][4];
            #pragma unroll
            for (int mt = 0; mt < 2; mt++) {
                uint32_t addr = sb + ao +
                    SW128((wm * 32 + mt * 16 + (lane & 15)) * 128 +
                          ks * 32 + ((lane >> 4) << 4));
                ldsm4(a[mt][0], a[mt][1], a[mt][2], a[mt][3], addr);
            }
            uint32_t b[8][2];
            #pragma unroll
            for (int p = 0; p < 4; p++) {
                uint32_t addr = sb + bo +
                    SW128((wn * 64 + p * 16 + (lane & 7) + ((lane >> 4) & 1) * 8) * 128 +
                          ks * 32 + ((lane >> 3) & 1) * 16);
                ldsm4(b[2 * p][0], b[2 * p][1], b[2 * p + 1][0], b[2 * p + 1][1], addr);
            }
            #pragma unroll
            for (int mt = 0; mt < 2; mt++)
                #pragma unroll
                for (int nt = 0; nt < 8; nt++)
                    mma_f16(acc[mt][nt], a[mt], b[nt][0], b[nt][1]);
        }
        buf = (buf + 1) % 3;
    }

    const int colbase = n0 + wn * 64;
    if (MODE == 0) {
        const int s = colbase >> 10;
        const int h = (colbase >> 6) & 15;
        __half* dst = (s == 0) ? Qh : ((s == 1) ? Kh : Vh);
        const float scl = (s == 0) ? QSCALE : 1.0f;
        #pragma unroll
        for (int mt = 0; mt < 2; mt++) {
            #pragma unroll
            for (int hf = 0; hf < 2; hf++) {
                int r = m0 + wm * 32 + mt * 16 + (lane >> 2) + hf * 8;
                int bidx = r >> 11, n = r & (NSEQ - 1);
                size_t rowoff = (((size_t)bidx * HH + h) * NSEQ + n) * DD;
                #pragma unroll
                for (int nt = 0; nt < 8; nt++) {
                    int dd = nt * 8 + (lane & 3) * 2;
                    float v0 = (acc[mt][nt][hf * 2 + 0] + bias[colbase + dd]) * scl;
                    float v1 = (acc[mt][nt][hf * 2 + 1] + bias[colbase + dd + 1]) * scl;
                    *(__half2*)&dst[rowoff + dd] =
                        __float22half2_rn(make_float2(v0, v1));
                }
            }
        }
    } else {
        #pragma unroll
        for (int mt = 0; mt < 2; mt++) {
            #pragma unroll
            for (int hf = 0; hf < 2; hf++) {
                int r = m0 + wm * 32 + mt * 16 + (lane >> 2) + hf * 8;
                float* crow2 = &Cout[(size_t)r * CC];
                #pragma unroll
                for (int nt = 0; nt < 8; nt++) {
                    int cc = colbase + nt * 8 + (lane & 3) * 2;
                    float2 o;
                    o.x = acc[mt][nt][hf * 2 + 0] + bias[cc];
                    o.y = acc[mt][nt][hf * 2 + 1] + bias[cc + 1];
                    *(float2*)&crow2[cc] = o;
                }
            }
        }
    }
}

// ---------------------------------------------------------------------------
// Flash attention — R14 variant + 6-stage KV ring + barrier every 4 iters.
// fp16 HMMA, log2 softmax, Q hoisted, rowsum via ones-MMA, V via ldsm4t,
// rescale skip. 2 CTAs/SM (smem 16 + 6*16 = 112.1KB/CTA -> 224.3KB/SM).
// Hazards (prefetch distance 2, ring of 6, barrier at kc%4==0):
//   WAR: write@kc (for kc+2) hits buf last read @kc-4; latest barrier b with
//        b >= kc-3 guarantees all threads finished iters <= b-1 >= kc-4.
//   RAW: same structure as the passing R14 kernel (issue distance 2 iters,
//        per-thread wait_group(1) before read).
// ---------------------------------------------------------------------------
#define FL_SQ 0u
#define FL_KV(buf) (16384u + (uint32_t)(buf) * 16384u)   /* K 8KB then V 8KB */
#define FL_NBUF 6
#define FL_SMEM (16384 + FL_NBUF * 16384 + 128)
#define NKB (NSEQ / 64)
#define ONES2 0x3C003C00u

__global__ __launch_bounds__(256, 2) void flash_mma_kernel(
    const __half* __restrict__ Qh, const __half* __restrict__ Kh,
    const __half* __restrict__ Vh, __half* __restrict__ Oh)
{
    extern __shared__ char smraw[];
    char* smp = (char*)(((uintptr_t)smraw + 127) & ~(uintptr_t)127);
    const uint32_t sb = smem_u32(smp);

    const int tid = threadIdx.x;
    const int lane = tid & 31, w = tid >> 5;
    const int bh = blockIdx.y;
    const int q0 = blockIdx.x * 128;
    const size_t base = (size_t)bh * NSEQ * DD;

    const char* gK = (const char*)(Kh + base);
    const char* gV = (const char*)(Vh + base);
    const int crow = tid >> 3;
    const int ccol = (tid & 7) * 16;

    auto load_kv = [&](int kc, int buf) {
        const size_t rb = (size_t)kc * 64 * 128;
        const uint32_t ko = FL_KV(buf), vo = ko + 8192u;
        #pragma unroll
        for (int i = 0; i < 2; i++) {
            int r = crow + i * 32;
            CP16(sb + ko + SW128(r * 128 + ccol), gK + rb + (size_t)r * 128 + ccol);
        }
        #pragma unroll
        for (int i = 0; i < 2; i++) {
            int r = crow + i * 32;
            CP16(sb + vo + SW128(r * 128 + ccol), gV + rb + (size_t)r * 128 + ccol);
        }
    };

    {
        const char* gQ = (const char*)(Qh + base + (size_t)q0 * DD);
        #pragma unroll
        for (int i = 0; i < 4; i++) {
            int r = crow + i * 32;
            CP16(sb + FL_SQ + SW128(r * 128 + ccol), gQ + (size_t)r * 128 + ccol);
        }
    }
    load_kv(0, 0); CP_COMMIT();
    load_kv(1, 1); CP_COMMIT();

    uint32_t qf[4][4];
    float oacc[8][4];
    #pragma unroll
    for (int nt = 0; nt < 8; nt++)
        #pragma unroll
        for (int j = 0; j < 4; j++) oacc[nt][j] = 0.f;
    float m0r = -1e30f, m1r = -1e30f, l0r = 0.f, l1r = 0.f;

    int buf = 0;
    for (int kc = 0; kc < NKB; kc++) {
        CP_WAIT1();
        if ((kc & 3) == 0) __syncthreads();
        if (kc + 2 < NKB) load_kv(kc + 2, (buf + 2) % FL_NBUF);
        CP_COMMIT();

        if (kc == 0) {
            #pragma unroll
            for (int ks = 0; ks < 4; ks++)
                ldsm4(qf[ks][0], qf[ks][1], qf[ks][2], qf[ks][3],
                      sb + FL_SQ + SW128((w * 16 + (lane & 15)) * 128 +
                                         ks * 32 + ((lane >> 4) << 4)));
        }
        const uint32_t ko = FL_KV(buf), vo = ko + 8192u;

        float sacc[8][4];
        #pragma unroll
        for (int nt = 0; nt < 8; nt++)
            #pragma unroll
            for (int j = 0; j < 4; j++) sacc[nt][j] = 0.f;

        #pragma unroll
        for (int ks = 0; ks < 4; ks++) {
            #pragma unroll
            for (int p = 0; p < 4; p++) {
                uint32_t b0, b1, b2, b3;
                ldsm4(b0, b1, b2, b3,
                      sb + ko + SW128((p * 16 + (lane & 7) + ((lane >> 4) & 1) * 8) * 128 +
                                      ks * 32 + ((lane >> 3) & 1) * 16));
                mma_f16(sacc[2 * p], qf[ks], b0, b1);
                mma_f16(sacc[2 * p + 1], qf[ks], b2, b3);
            }
        }

        float mx0 = m0r, mx1 = m1r;
        #pragma unroll
        for (int nt = 0; nt < 8; nt++) {
            mx0 = fmaxf(mx0, fmaxf(sacc[nt][0], sacc[nt][1]));
            mx1 = fmaxf(mx1, fmaxf(sacc[nt][2], sacc[nt][3]));
        }
        mx0 = fmaxf(mx0, __shfl_xor_sync(0xffffffffu, mx0, 1));
        mx0 = fmaxf(mx0, __shfl_xor_sync(0xffffffffu, mx0, 2));
        mx1 = fmaxf(mx1, __shfl_xor_sync(0xffffffffu, mx1, 1));
        mx1 = fmaxf(mx1, __shfl_xor_sync(0xffffffffu, mx1, 2));

        float alpha0 = ex2_f32(m0r - mx0);
        float alpha1 = ex2_f32(m1r - mx1);
        m0r = mx0; m1r = mx1;

        if (__any_sync(0xffffffffu, (alpha0 != 1.f) || (alpha1 != 1.f))) {
            #pragma unroll
            for (int nt = 0; nt < 8; nt++) {
                oacc[nt][0] *= alpha0; oacc[nt][1] *= alpha0;
                oacc[nt][2] *= alpha1; oacc[nt][3] *= alpha1;
            }
        }

        float ssum[4] = {0.f, 0.f, 0.f, 0.f};
        #pragma unroll
        for (int kt = 0; kt < 4; kt++) {
            uint32_t pa[4];
            pa[0] = ex2_h2(pack_h2(sacc[2 * kt][0] - mx0,     sacc[2 * kt][1] - mx0));
            pa[1] = ex2_h2(pack_h2(sacc[2 * kt][2] - mx1,     sacc[2 * kt][3] - mx1));
            pa[2] = ex2_h2(pack_h2(sacc[2 * kt + 1][0] - mx0, sacc[2 * kt + 1][1] - mx0));
            pa[3] = ex2_h2(pack_h2(sacc[2 * kt + 1][2] - mx1, sacc[2 * kt + 1][3] - mx1));
            mma_f16(ssum, pa, ONES2, ONES2);
            #pragma unroll
            for (int ntp = 0; ntp < 4; ntp++) {
                uint32_t v0, v1, v2, v3;
                ldsm4t(v0, v1, v2, v3,
                       sb + vo + SW128((kt * 16 + (lane & 15)) * 128 +
                                       ntp * 32 + ((lane >> 4) << 4)));
                mma_f16(oacc[2 * ntp],     pa, v0, v1);
                mma_f16(oacc[2 * ntp + 1], pa, v2, v3);
            }
        }
        l0r = l0r * alpha0 + ssum[0];
        l1r = l1r * alpha1 + ssum[2];

        buf = (buf + 1) % FL_NBUF;
    }

    const float inv0 = 1.f / l0r, inv1 = 1.f / l1r;
    const int b = bh >> 4, h = bh & 15;
    #pragma unroll
    for (int hf = 0; hf < 2; hf++) {
        int n = q0 + w * 16 + (lane >> 2) + hf * 8;
        float inv = hf ? inv1 : inv0;
        __half* orow = Oh + ((size_t)b * NSEQ + n) * CC;
        #pragma unroll
        for (int nt = 0; nt < 8; nt++) {
            int col = h * 64 + nt * 8 + (lane & 3) * 2;
            float o0 = oacc[nt][hf * 2 + 0] * inv;
            float o1 = oacc[nt][hf * 2 + 1] * inv;
            *(__half2*)&orow[col] = __float22half2_rn(make_float2(o0, o1));
        }
    }
}

// ---------------------------------------------------------------------------
// Launcher
// ---------------------------------------------------------------------------
extern "C" void kernel_launch(void* const* d_in, const int* in_sizes, int n_in,
                              void* d_out, int out_size)
{
    const float* x     = (const float*)d_in[0];
    const float* W_qkv = (const float*)d_in[1];
    const float* b_qkv = (const float*)d_in[2];
    const float* W_out = (const float*)d_in[3];
    const float* b_out = (const float*)d_in[4];
    float* out = (float*)d_out;

    __half *qh, *kh, *vh, *xh, *Oh, *Bq, *Bo;
    cudaGetSymbolAddress((void**)&qh, g_qh);
    cudaGetSymbolAddress((void**)&kh, g_kh);
    cudaGetSymbolAddress((void**)&vh, g_vh);
    cudaGetSymbolAddress((void**)&xh, g_xh);
    cudaGetSymbolAddress((void**)&Oh, g_Oh);
    cudaGetSymbolAddress((void**)&Bq, g_Bq);
    cudaGetSymbolAddress((void**)&Bo, g_Bo);

    cudaFuncSetAttribute((const void*)mma_gemm_kernel<0>,
                         cudaFuncAttributeMaxDynamicSharedMemorySize, GEMM_SMEM);
    cudaFuncSetAttribute((const void*)mma_gemm_kernel<1>,
                         cudaFuncAttributeMaxDynamicSharedMemorySize, GEMM_SMEM);
    cudaFuncSetAttribute(flash_mma_kernel,
                         cudaFuncAttributeMaxDynamicSharedMemorySize, FL_SMEM);

    // 1) fused prep: cast x; transpose+cast W_qkv, W_out (K-major)
    prep_kernel<<<NB_CAST + NB_TQ + NB_TO, 256>>>(x, W_qkv, W_out, xh, Bq, Bo);
    // 2) QKV projection (HMMA fp16, K=1024) -> fp16 Q(log2-scaled)/K/V
    mma_gemm_kernel<0><<<dim3(K3 / 128, MM / 128), 256, GEMM_SMEM>>>(
        xh, Bq, b_qkv, nullptr, qh, kh, vh);
    // 3) Flash attention (6-stage ring, barrier/4 iters) -> Oh [B,N,C] fp16
    flash_mma_kernel<<<dim3(NSEQ / 128, BB * HH), 256, FL_SMEM>>>(qh, kh, vh, Oh);
    // 4) Output projection -> out
    mma_gemm_kernel<1><<<dim3(CC / 128, MM / 128), 256, GEMM_SMEM>>>(
        Oh, Bo, b_out, out, nullptr, nullptr, nullptr);
}

// round 16
// speedup vs baseline: 1.6340x; 1.0029x over previous
#include <cuda_runtime.h>
#include <cuda_fp16.h>
#include <math.h>
#include <stdint.h>

#define BB 2
#define HH 16
#define NSEQ 2048
#define DD 64
#define CC 1024
#define MM (BB*NSEQ)      /* 4096 */
#define K3 (3*CC)         /* 3072 */

// ---------------------------------------------------------------------------
// Scratch (__device__ globals; allocation-free rule)
// ---------------------------------------------------------------------------
__device__ __align__(256) __half g_qh[(size_t)BB*HH*NSEQ*DD];   // Q fp16, pre-scaled 0.125*log2e
__device__ __align__(256) __half g_kh[(size_t)BB*HH*NSEQ*DD];
__device__ __align__(256) __half g_vh[(size_t)BB*HH*NSEQ*DD];
__device__ __align__(256) __half g_xh[(size_t)MM*CC];           // x cast to fp16
__device__ __align__(256) __half g_Oh[(size_t)MM*CC];           // attention out, fp16
__device__ __align__(256) __half g_Bq[(size_t)K3*CC];           // W_qkv fp16 K-major
__device__ __align__(256) __half g_Bo[(size_t)CC*CC];           // W_out fp16 K-major

// ---------------------------------------------------------------------------
// PTX helpers (baseline sm_80 ISA — safe on plain sm_103 target)
// ---------------------------------------------------------------------------
__device__ __forceinline__ uint32_t smem_u32(const void* p) {
    uint32_t a;
    asm("{ .reg .u64 t; cvta.to.shared.u64 t, %1; cvt.u32.u64 %0, t; }"
        : "=r"(a) : "l"(p));
    return a;
}

#define SW128(off) ((off) ^ (((off) >> 3) & 0x70))

#define CP16(dst, src) \
    asm volatile("cp.async.cg.shared.global [%0], [%1], 16;" :: "r"(dst), "l"(src))
#define CP_COMMIT() asm volatile("cp.async.commit_group;" ::: "memory")
#define CP_WAIT1()  asm volatile("cp.async.wait_group 1;" ::: "memory")

__device__ __forceinline__ void ldsm4(uint32_t& r0, uint32_t& r1,
                                      uint32_t& r2, uint32_t& r3, uint32_t a) {
    asm volatile("ldmatrix.sync.aligned.m8n8.x4.shared.b16 {%0,%1,%2,%3}, [%4];"
        : "=r"(r0), "=r"(r1), "=r"(r2), "=r"(r3) : "r"(a));
}
__device__ __forceinline__ void ldsm4t(uint32_t& r0, uint32_t& r1,
                                       uint32_t& r2, uint32_t& r3, uint32_t a) {
    asm volatile("ldmatrix.sync.aligned.m8n8.x4.trans.shared.b16 {%0,%1,%2,%3}, [%4];"
        : "=r"(r0), "=r"(r1), "=r"(r2), "=r"(r3) : "r"(a));
}
__device__ __forceinline__ void mma_f16(float* c, const uint32_t* a, uint32_t b0, uint32_t b1) {
    asm volatile("mma.sync.aligned.m16n8k16.row.col.f32.f16.f16.f32 "
        "{%0,%1,%2,%3}, {%4,%5,%6,%7}, {%8,%9}, {%0,%1,%2,%3};"
        : "+f"(c[0]), "+f"(c[1]), "+f"(c[2]), "+f"(c[3])
        : "r"(a[0]), "r"(a[1]), "r"(a[2]), "r"(a[3]), "r"(b0), "r"(b1));
}

__device__ __forceinline__ uint32_t pack_h2(float lo, float hi) {
    __half2 h = __float22half2_rn(make_float2(lo, hi));
    return *(uint32_t*)&h;
}
__device__ __forceinline__ uint32_t ex2_h2(uint32_t x) {
    uint32_t r;
    asm("ex2.approx.f16x2 %0, %1;" : "=r"(r) : "r"(x));
    return r;
}
__device__ __forceinline__ float ex2_f32(float x) {
    float r;
    asm("ex2.approx.f32 %0, %1;" : "=f"(r) : "f"(x));
    return r;
}

// ---------------------------------------------------------------------------
// Fused prep: cast x->fp16 (8 elems/thread), transpose+cast weights (K-major)
// with vectorized uint2 (4-half) stores.
// ---------------------------------------------------------------------------
#define NB_CAST (MM * CC / 2048)          /* 2048: 8 floats per thread */
#define NB_TQ   ((CC / 32) * (K3 / 32))   /* 3072 */
#define NB_TO   ((CC / 32) * (CC / 32))   /* 1024 */

__global__ __launch_bounds__(256) void prep_kernel(
    const float* __restrict__ x,  const float* __restrict__ Wq,
    const float* __restrict__ Wo, __half* __restrict__ xh,
    __half* __restrict__ Bq, __half* __restrict__ Bo)
{
    const int bid = blockIdx.x, tid = threadIdx.x;
    if (bid < NB_CAST) {
        size_t idx8 = ((size_t)bid * 256 + tid) * 8;
        float4 v0 = *(const float4*)&x[idx8];
        float4 v1 = *(const float4*)&x[idx8 + 4];
        __half2 a = __float22half2_rn(make_float2(v0.x, v0.y));
        __half2 b = __float22half2_rn(make_float2(v0.z, v0.w));
        __half2 c = __float22half2_rn(make_float2(v1.x, v1.y));
        __half2 d = __float22half2_rn(make_float2(v1.z, v1.w));
        *(uint4*)&xh[idx8] = make_uint4(*(uint32_t*)&a, *(uint32_t*)&b,
                                        *(uint32_t*)&c, *(uint32_t*)&d);
        return;
    }
    const float* W; __half* Bd; int N, b;
    if (bid < NB_CAST + NB_TQ) { b = bid - NB_CAST; W = Wq; Bd = Bq; N = K3; }
    else                       { b = bid - NB_CAST - NB_TQ; W = Wo; Bd = Bo; N = CC; }
    const int k0 = (b % 32) * 32;
    const int n0 = (b / 32) * 32;
    const int tx = tid & 31, ty = tid >> 5;

    __shared__ float t[32][33];
    #pragma unroll
    for (int i = 0; i < 4; i++)
        t[ty + i * 8][tx] = W[(size_t)(k0 + ty + i * 8) * N + n0 + tx];
    __syncthreads();

    // epilogue: thread -> (n = tid>>3, k-group = (tid&7)*4); one uint2 store
    const int n = tid >> 3;
    const int g = (tid & 7) * 4;
    __half2 p0 = __float22half2_rn(make_float2(t[g + 0][n], t[g + 1][n]));
    __half2 p1 = __float22half2_rn(make_float2(t[g + 2][n], t[g + 3][n]));
    *(uint2*)&Bd[(size_t)(n0 + n) * CC + k0 + g] =
        make_uint2(*(uint32_t*)&p0, *(uint32_t*)&p1);
}

// ---------------------------------------------------------------------------
// HMMA GEMM: D[M][N] = A[M][1024] @ B[N][1024]^T (+bias)   (R8 verbatim)
// BM=128, BN=128, BK=64, 3-stage cp.async, 1 sync/iter, 2 CTAs/SM.
// ---------------------------------------------------------------------------
#define STAGE_BYTES 32768
#define GEMM_SMEM (3 * STAGE_BYTES + 128)
#define KEXT 1024
#define KITERS (KEXT / 64)
#define QSCALE 0.18033688f   /* 0.125 * log2(e) */

template<int MODE>
__global__ __launch_bounds__(256, 2) void mma_gemm_kernel(
    const __half* __restrict__ A,
    const __half* __restrict__ Bm,
    const float* __restrict__ bias,
    float* __restrict__ Cout,
    __half* __restrict__ Qh, __half* __restrict__ Kh, __half* __restrict__ Vh)
{
    extern __shared__ char smraw[];
    char* smp = (char*)(((uintptr_t)smraw + 127) & ~(uintptr_t)127);
    const uint32_t sb = smem_u32(smp);

    const int tid = threadIdx.x;
    const int lane = tid & 31, wid = tid >> 5;
    const int wm = wid & 3, wn = wid >> 2;
    const int m0 = blockIdx.y * 128;
    const int n0 = blockIdx.x * 128;

    const char* gA = (const char*)A + (size_t)m0 * (KEXT * 2);
    const char* gB = (const char*)Bm + (size_t)n0 * (KEXT * 2);

    const int crow = tid >> 3;
    const int ccol = (tid & 7) * 16;

    auto load_tile = [&](int it, int buf) {
        const uint32_t ao = (uint32_t)buf * STAGE_BYTES;
        const uint32_t bo = ao + 16384u;
        const size_t kbyte = (size_t)it * 128;
        #pragma unroll
        for (int i = 0; i < 4; i++) {
            int r = crow + i * 32;
            CP16(sb + ao + SW128(r * 128 + ccol),
                 gA + (size_t)r * (KEXT * 2) + kbyte + ccol);
        }
        #pragma unroll
        for (int i = 0; i < 4; i++) {
            int r = crow + i * 32;
            CP16(sb + bo + SW128(r * 128 + ccol),
                 gB + (size_t)r * (KEXT * 2) + kbyte + ccol);
        }
    };

    float acc[2][8][4];
    #pragma unroll
    for (int mt = 0; mt < 2; mt++)
        #pragma unroll
        for (int nt = 0; nt < 8; nt++)
            #pragma unroll
            for (int j = 0; j < 4; j++) acc[mt][nt][j] = 0.f;

    load_tile(0, 0); CP_COMMIT();
    load_tile(1, 1); CP_COMMIT();

    int buf = 0;
    for (int it = 0; it < KITERS; it++) {
        CP_WAIT1();
        __syncthreads();
        if (it + 2 < KITERS) load_tile(it + 2, (buf + 2) % 3);
        CP_COMMIT();

        const uint32_t ao = (uint32_t)buf * STAGE_BYTES;
        const uint32_t bo = ao + 16384u;

        #pragma unroll
        for (int ks = 0; ks < 4; ks++) {
            uint32_t a[2][4];
            #pragma unroll
            for (int mt = 0; mt < 2; mt++) {
                uint32_t addr = sb + ao +
                    SW128((wm * 32 + mt * 16 + (lane & 15)) * 128 +
                          ks * 32 + ((lane >> 4) << 4));
                ldsm4(a[mt][0], a[mt][1], a[mt][2], a[mt][3], addr);
            }
            uint32_t b[8][2];
            #pragma unroll
            for (int p = 0; p < 4; p++) {
                uint32_t addr = sb + bo +
                    SW128((wn * 64 + p * 16 + (lane & 7) + ((lane >> 4) & 1) * 8) * 128 +
                          ks * 32 + ((lane >> 3) & 1) * 16);
                ldsm4(b[2 * p][0], b[2 * p][1], b[2 * p + 1][0], b[2 * p + 1][1], addr);
            }
            #pragma unroll
            for (int mt = 0; mt < 2; mt++)
                #pragma unroll
                for (int nt = 0; nt < 8; nt++)
                    mma_f16(acc[mt][nt], a[mt], b[nt][0], b[nt][1]);
        }
        buf = (buf + 1) % 3;
    }

    const int colbase = n0 + wn * 64;
    if (MODE == 0) {
        const int s = colbase >> 10;
        const int h = (colbase >> 6) & 15;
        __half* dst = (s == 0) ? Qh : ((s == 1) ? Kh : Vh);
        const float scl = (s == 0) ? QSCALE : 1.0f;
        #pragma unroll
        for (int mt = 0; mt < 2; mt++) {
            #pragma unroll
            for (int hf = 0; hf < 2; hf++) {
                int r = m0 + wm * 32 + mt * 16 + (lane >> 2) + hf * 8;
                int bidx = r >> 11, n = r & (NSEQ - 1);
                size_t rowoff = (((size_t)bidx * HH + h) * NSEQ + n) * DD;
                #pragma unroll
                for (int nt = 0; nt < 8; nt++) {
                    int dd = nt * 8 + (lane & 3) * 2;
                    float v0 = (acc[mt][nt][hf * 2 + 0] + bias[colbase + dd]) * scl;
                    float v1 = (acc[mt][nt][hf * 2 + 1] + bias[colbase + dd + 1]) * scl;
                    *(__half2*)&dst[rowoff + dd] =
                        __float22half2_rn(make_float2(v0, v1));
                }
            }
        }
    } else {
        #pragma unroll
        for (int mt = 0; mt < 2; mt++) {
            #pragma unroll
            for (int hf = 0; hf < 2; hf++) {
                int r = m0 + wm * 32 + mt * 16 + (lane >> 2) + hf * 8;
                float* crow2 = &Cout[(size_t)r * CC];
                #pragma unroll
                for (int nt = 0; nt < 8; nt++) {
                    int cc = colbase + nt * 8 + (lane & 3) * 2;
                    float2 o;
                    o.x = acc[mt][nt][hf * 2 + 0] + bias[cc];
                    o.y = acc[mt][nt][hf * 2 + 1] + bias[cc + 1];
                    *(float2*)&crow2[cc] = o;
                }
            }
        }
    }
}

// ---------------------------------------------------------------------------
// Flash attention — R15 verbatim: 6-stage KV ring, barrier every 4 iters,
// fp16 HMMA, log2 softmax, Q hoisted, rowsum via ones-MMA, V via ldsm4t,
// rescale skip. 2 CTAs/SM (112.1KB/CTA -> 224.3KB/SM).
// ---------------------------------------------------------------------------
#define FL_SQ 0u
#define FL_KV(buf) (16384u + (uint32_t)(buf) * 16384u)   /* K 8KB then V 8KB */
#define FL_NBUF 6
#define FL_SMEM (16384 + FL_NBUF * 16384 + 128)
#define NKB (NSEQ / 64)
#define ONES2 0x3C003C00u

__global__ __launch_bounds__(256, 2) void flash_mma_kernel(
    const __half* __restrict__ Qh, const __half* __restrict__ Kh,
    const __half* __restrict__ Vh, __half* __restrict__ Oh)
{
    extern __shared__ char smraw[];
    char* smp = (char*)(((uintptr_t)smraw + 127) & ~(uintptr_t)127);
    const uint32_t sb = smem_u32(smp);

    const int tid = threadIdx.x;
    const int lane = tid & 31, w = tid >> 5;
    const int bh = blockIdx.y;
    const int q0 = blockIdx.x * 128;
    const size_t base = (size_t)bh * NSEQ * DD;

    const char* gK = (const char*)(Kh + base);
    const char* gV = (const char*)(Vh + base);
    const int crow = tid >> 3;
    const int ccol = (tid & 7) * 16;

    auto load_kv = [&](int kc, int buf) {
        const size_t rb = (size_t)kc * 64 * 128;
        const uint32_t ko = FL_KV(buf), vo = ko + 8192u;
        #pragma unroll
        for (int i = 0; i < 2; i++) {
            int r = crow + i * 32;
            CP16(sb + ko + SW128(r * 128 + ccol), gK + rb + (size_t)r * 128 + ccol);
        }
        #pragma unroll
        for (int i = 0; i < 2; i++) {
            int r = crow + i * 32;
            CP16(sb + vo + SW128(r * 128 + ccol), gV + rb + (size_t)r * 128 + ccol);
        }
    };

    {
        const char* gQ = (const char*)(Qh + base + (size_t)q0 * DD);
        #pragma unroll
        for (int i = 0; i < 4; i++) {
            int r = crow + i * 32;
            CP16(sb + FL_SQ + SW128(r * 128 + ccol), gQ + (size_t)r * 128 + ccol);
        }
    }
    load_kv(0, 0); CP_COMMIT();
    load_kv(1, 1); CP_COMMIT();

    uint32_t qf[4][4];
    float oacc[8][4];
    #pragma unroll
    for (int nt = 0; nt < 8; nt++)
        #pragma unroll
        for (int j = 0; j < 4; j++) oacc[nt][j] = 0.f;
    float m0r = -1e30f, m1r = -1e30f, l0r = 0.f, l1r = 0.f;

    int buf = 0;
    for (int kc = 0; kc < NKB; kc++) {
        CP_WAIT1();
        if ((kc & 3) == 0) __syncthreads();
        if (kc + 2 < NKB) load_kv(kc + 2, (buf + 2) % FL_NBUF);
        CP_COMMIT();

        if (kc == 0) {
            #pragma unroll
            for (int ks = 0; ks < 4; ks++)
                ldsm4(qf[ks][0], qf[ks][1], qf[ks][2], qf[ks][3],
                      sb + FL_SQ + SW128((w * 16 + (lane & 15)) * 128 +
                                         ks * 32 + ((lane >> 4) << 4)));
        }
        const uint32_t ko = FL_KV(buf), vo = ko + 8192u;

        float sacc[8][4];
        #pragma unroll
        for (int nt = 0; nt < 8; nt++)
            #pragma unroll
            for (int j = 0; j < 4; j++) sacc[nt][j] = 0.f;

        #pragma unroll
        for (int ks = 0; ks < 4; ks++) {
            #pragma unroll
            for (int p = 0; p < 4; p++) {
                uint32_t b0, b1, b2, b3;
                ldsm4(b0, b1, b2, b3,
                      sb + ko + SW128((p * 16 + (lane & 7) + ((lane >> 4) & 1) * 8) * 128 +
                                      ks * 32 + ((lane >> 3) & 1) * 16));
                mma_f16(sacc[2 * p], qf[ks], b0, b1);
                mma_f16(sacc[2 * p + 1], qf[ks], b2, b3);
            }
        }

        float mx0 = m0r, mx1 = m1r;
        #pragma unroll
        for (int nt = 0; nt < 8; nt++) {
            mx0 = fmaxf(mx0, fmaxf(sacc[nt][0], sacc[nt][1]));
            mx1 = fmaxf(mx1, fmaxf(sacc[nt][2], sacc[nt][3]));
        }
        mx0 = fmaxf(mx0, __shfl_xor_sync(0xffffffffu, mx0, 1));
        mx0 = fmaxf(mx0, __shfl_xor_sync(0xffffffffu, mx0, 2));
        mx1 = fmaxf(mx1, __shfl_xor_sync(0xffffffffu, mx1, 1));
        mx1 = fmaxf(mx1, __shfl_xor_sync(0xffffffffu, mx1, 2));

        float alpha0 = ex2_f32(m0r - mx0);
        float alpha1 = ex2_f32(m1r - mx1);
        m0r = mx0; m1r = mx1;

        if (__any_sync(0xffffffffu, (alpha0 != 1.f) || (alpha1 != 1.f))) {
            #pragma unroll
            for (int nt = 0; nt < 8; nt++) {
                oacc[nt][0] *= alpha0; oacc[nt][1] *= alpha0;
                oacc[nt][2] *= alpha1; oacc[nt][3] *= alpha1;
            }
        }

        float ssum[4] = {0.f, 0.f, 0.f, 0.f};
        #pragma unroll
        for (int kt = 0; kt < 4; kt++) {
            uint32_t pa[4];
            pa[0] = ex2_h2(pack_h2(sacc[2 * kt][0] - mx0,     sacc[2 * kt][1] - mx0));
            pa[1] = ex2_h2(pack_h2(sacc[2 * kt][2] - mx1,     sacc[2 * kt][3] - mx1));
            pa[2] = ex2_h2(pack_h2(sacc[2 * kt + 1][0] - mx0, sacc[2 * kt + 1][1] - mx0));
            pa[3] = ex2_h2(pack_h2(sacc[2 * kt + 1][2] - mx1, sacc[2 * kt + 1][3] - mx1));
            mma_f16(ssum, pa, ONES2, ONES2);
            #pragma unroll
            for (int ntp = 0; ntp < 4; ntp++) {
                uint32_t v0, v1, v2, v3;
                ldsm4t(v0, v1, v2, v3,
                       sb + vo + SW128((kt * 16 + (lane & 15)) * 128 +
                                       ntp * 32 + ((lane >> 4) << 4)));
                mma_f16(oacc[2 * ntp],     pa, v0, v1);
                mma_f16(oacc[2 * ntp + 1], pa, v2, v3);
            }
        }
        l0r = l0r * alpha0 + ssum[0];
        l1r = l1r * alpha1 + ssum[2];

        buf = (buf + 1) % FL_NBUF;
    }

    const float inv0 = 1.f / l0r, inv1 = 1.f / l1r;
    const int b = bh >> 4, h = bh & 15;
    #pragma unroll
    for (int hf = 0; hf < 2; hf++) {
        int n = q0 + w * 16 + (lane >> 2) + hf * 8;
        float inv = hf ? inv1 : inv0;
        __half* orow = Oh + ((size_t)b * NSEQ + n) * CC;
        #pragma unroll
        for (int nt = 0; nt < 8; nt++) {
            int col = h * 64 + nt * 8 + (lane & 3) * 2;
            float o0 = oacc[nt][hf * 2 + 0] * inv;
            float o1 = oacc[nt][hf * 2 + 1] * inv;
            *(__half2*)&orow[col] = __float22half2_rn(make_float2(o0, o1));
        }
    }
}

// ---------------------------------------------------------------------------
// Launcher
// ---------------------------------------------------------------------------
extern "C" void kernel_launch(void* const* d_in, const int* in_sizes, int n_in,
                              void* d_out, int out_size)
{
    const float* x     = (const float*)d_in[0];
    const float* W_qkv = (const float*)d_in[1];
    const float* b_qkv = (const float*)d_in[2];
    const float* W_out = (const float*)d_in[3];
    const float* b_out = (const float*)d_in[4];
    float* out = (float*)d_out;

    __half *qh, *kh, *vh, *xh, *Oh, *Bq, *Bo;
    cudaGetSymbolAddress((void**)&qh, g_qh);
    cudaGetSymbolAddress((void**)&kh, g_kh);
    cudaGetSymbolAddress((void**)&vh, g_vh);
    cudaGetSymbolAddress((void**)&xh, g_xh);
    cudaGetSymbolAddress((void**)&Oh, g_Oh);
    cudaGetSymbolAddress((void**)&Bq, g_Bq);
    cudaGetSymbolAddress((void**)&Bo, g_Bo);

    cudaFuncSetAttribute((const void*)mma_gemm_kernel<0>,
                         cudaFuncAttributeMaxDynamicSharedMemorySize, GEMM_SMEM);
    cudaFuncSetAttribute((const void*)mma_gemm_kernel<1>,
                         cudaFuncAttributeMaxDynamicSharedMemorySize, GEMM_SMEM);
    cudaFuncSetAttribute(flash_mma_kernel,
                         cudaFuncAttributeMaxDynamicSharedMemorySize, FL_SMEM);

    // 1) fused prep: cast x (8/thread); transpose+cast W_qkv, W_out (uint2 stores)
    prep_kernel<<<NB_CAST + NB_TQ + NB_TO, 256>>>(x, W_qkv, W_out, xh, Bq, Bo);
    // 2) QKV projection (HMMA fp16, K=1024) -> fp16 Q(log2-scaled)/K/V
    mma_gemm_kernel<0><<<dim3(K3 / 128, MM / 128), 256, GEMM_SMEM>>>(
        xh, Bq, b_qkv, nullptr, qh, kh, vh);
    // 3) Flash attention (6-stage ring, barrier/4 iters) -> Oh [B,N,C] fp16
    flash_mma_kernel<<<dim3(NSEQ / 128, BB * HH), 256, FL_SMEM>>>(qh, kh, vh, Oh);
    // 4) Output projection -> out
    mma_gemm_kernel<1><<<dim3(CC / 128, MM / 128), 256, GEMM_SMEM>>>(
        Oh, Bo, b_out, out, nullptr, nullptr, nullptr);
}